// round 11
// baseline (speedup 1.0000x reference)
#include <cuda_runtime.h>
#include <cuda_bf16.h>
#include <math.h>
#include <stdint.h>

// ============================================================================
// N=16, SEQ=20, P=32*32=1024, VD=256, HN=512, EMB=300, NHEAD=2, DH=128
// conv input channels: feat 0..255, spatial 256..263, hn 264..775
// Split-bf16 GEMM on mma.sync (HMMA): C = Ah*Bh + Ah*Bl + Al*Bh  (~1e-5 err)
// R10: resubmit of R9 (infra failure, no measurement): fused split-products,
// cp.async staging, dyn smem 80KB, occ 2.
// ============================================================================

#define DIV_UP(a,b) (((a)+(b)-1)/(b))

__device__ __forceinline__ void split_bf16(float v, __nv_bfloat16& h, __nv_bfloat16& l) {
    h = __float2bfloat16(v);
    l = __float2bfloat16(v - __bfloat162float(h));
}

__device__ __forceinline__ void ldsm4(uint32_t* d, const void* p) {
    uint32_t addr = (uint32_t)__cvta_generic_to_shared(p);
    asm volatile("ldmatrix.sync.aligned.m8n8.x4.shared.b16 {%0,%1,%2,%3}, [%4];"
        : "=r"(d[0]), "=r"(d[1]), "=r"(d[2]), "=r"(d[3]) : "r"(addr));
}
__device__ __forceinline__ void ldsm2(uint32_t* d, const void* p) {
    uint32_t addr = (uint32_t)__cvta_generic_to_shared(p);
    asm volatile("ldmatrix.sync.aligned.m8n8.x2.shared.b16 {%0,%1}, [%2];"
        : "=r"(d[0]), "=r"(d[1]) : "r"(addr));
}
__device__ __forceinline__ void mma16816(float* c, const uint32_t* a, const uint32_t* b) {
    asm volatile("mma.sync.aligned.m16n8k16.row.col.f32.bf16.bf16.f32 "
        "{%0,%1,%2,%3}, {%4,%5,%6,%7}, {%8,%9}, {%0,%1,%2,%3};"
        : "+f"(c[0]), "+f"(c[1]), "+f"(c[2]), "+f"(c[3])
        : "r"(a[0]), "r"(a[1]), "r"(a[2]), "r"(a[3]), "r"(b[0]), "r"(b[1]));
}
__device__ __forceinline__ void cp16(uint32_t dst, const void* src, int src_size) {
    asm volatile("cp.async.ca.shared.global [%0], [%1], 16, %2;"
        :: "r"(dst), "l"(src), "r"(src_size) : "memory");
}
__device__ __forceinline__ void cp_commit() {
    asm volatile("cp.async.commit_group;" ::: "memory");
}
template<int N> __device__ __forceinline__ void cp_wait() {
    asm volatile("cp.async.wait_group %0;" :: "n"(N) : "memory");
}

// ---------------- scratch (device globals) -----------------------------------
__device__ __nv_bfloat16 g_fb_h [16*1024*256], g_fb_l [16*1024*256];  // feat (n,p,c)
__device__ __nv_bfloat16 g_tln_h[16384*256],   g_tln_l[16384*256];
__device__ __nv_bfloat16 g_ob_h [16384*256],   g_ob_l [16384*256];
__device__ __nv_bfloat16 g_fea_h[16384*256],   g_fea_l[16384*256];
__device__ __nv_bfloat16 g_h1_h [16384*256],   g_h1_l [16384*256];
__device__ __nv_bfloat16 g_wi_h [768*256],     g_wi_l [768*256];      // in_proj
__device__ __nv_bfloat16 g_wo_h [256*256],     g_wo_l [256*256];
__device__ __nv_bfloat16 g_w1_h [256*256],     g_w1_l [256*256];
__device__ __nv_bfloat16 g_w2_h [256*256],     g_w2_l [256*256];
__device__ __nv_bfloat16 g_bd_h [256*2304],    g_bd_l [256*2304];     // conv weights
__device__ float g_t   [16384*256];
__device__ float g_tln [16384*256];
__device__ float g_kv  [16384*512];
__device__ float g_x1  [16384*256];
__device__ float g_fea [16384*256];
__device__ float g_x2  [16384*256];
__device__ float g_Wsum[9*512*256];
__device__ float g_Hb  [16*9*256];
__device__ float g_Sb  [1024*256];
__device__ float g_qt  [320*256];
__device__ float g_qh  [320*256];

// ---------------- init / precompute ------------------------------------------
__global__ void k_init_feat(const float* __restrict__ feature, float* __restrict__ dout) {
    int idx = blockIdx.x * blockDim.x + threadIdx.x;   // NCHW linear
    if (idx >= 16*256*1024) return;
    int n = idx >> 18;
    int r = idx & 262143;
    int c = r >> 10;
    int p = r & 1023;
    float v = feature[idx];
    dout[idx] = v;
    __nv_bfloat16 h, l; split_bf16(v, h, l);
    size_t o = (size_t)((n << 10) + p) * 256 + c;
    g_fb_h[o] = h; g_fb_l[o] = l;
}

__global__ void k_repack(const float* __restrict__ w) {
    int idx = blockIdx.x * blockDim.x + threadIdx.x;
    if (idx >= 256*2304) return;
    int co  = idx / 2304;
    int k   = idx % 2304;
    int tap = k >> 8;
    int ci  = k & 255;
    int kh = tap / 3, kw = tap % 3;
    float v = w[((co*776 + ci)*3 + kh)*3 + kw];
    __nv_bfloat16 h, l; split_bf16(v, h, l);
    g_bd_h[idx] = h; g_bd_l[idx] = l;
}

__global__ void k_split(const float* __restrict__ src, __nv_bfloat16* __restrict__ h,
                        __nv_bfloat16* __restrict__ l, int n) {
    int i = blockIdx.x * blockDim.x + threadIdx.x;
    if (i >= n) return;
    __nv_bfloat16 hh, ll; split_bf16(src[i], hh, ll);
    h[i] = hh; l[i] = ll;
}

__global__ void k_wsum(const float* __restrict__ w) {
    int idx = blockIdx.x * blockDim.x + threadIdx.x;
    if (idx >= 9*512*256) return;
    int co   = idx & 255;
    int tmp  = idx >> 8;
    int ci   = tmp & 511;
    int type = tmp >> 9;
    int ty = type / 3, tx = type % 3;
    int kh0 = (ty == 0) ? 1 : 0, kh1 = (ty == 2) ? 1 : 2;
    int kw0 = (tx == 0) ? 1 : 0, kw1 = (tx == 2) ? 1 : 2;
    float s = 0.f;
    for (int kh = kh0; kh <= kh1; kh++)
        for (int kw = kw0; kw <= kw1; kw++)
            s += w[((co*776 + 264 + ci)*3 + kh)*3 + kw];
    g_Wsum[idx] = s;
}

__global__ void k_hb(const float* __restrict__ hn) {
    int idx = blockIdx.x * blockDim.x + threadIdx.x;
    if (idx >= 16*9*256) return;
    int co   = idx & 255;
    int type = (idx >> 8) % 9;
    int n    = idx / 2304;
    const float* hr = hn + n * 512;
    const float* wr = g_Wsum + type * 512 * 256 + co;
    float s = 0.f;
    for (int ci = 0; ci < 512; ci++) s += hr[ci] * wr[ci * 256];
    g_Hb[idx] = s;
}

__device__ __forceinline__ float spatial_val(int ci, int yy, int xx) {
    const float inv = 1.f / 32.f;
    switch (ci) {
        case 0: return xx * (2.f*inv) - 1.f;
        case 1: return yy * (2.f*inv) - 1.f;
        case 2: return (xx + 1) * (2.f*inv) - 1.f;
        case 3: return (yy + 1) * (2.f*inv) - 1.f;
        case 4: return (xx + 0.5f) * (2.f*inv) - 1.f;
        case 5: return (yy + 0.5f) * (2.f*inv) - 1.f;
        default: return inv;
    }
}

__global__ void k_sb(const float* __restrict__ w) {
    int idx = blockIdx.x * blockDim.x + threadIdx.x;
    if (idx >= 1024*256) return;
    int co = idx & 255;
    int p  = idx >> 8;
    int y = p >> 5, x = p & 31;
    float s = 0.f;
    for (int kh = 0; kh < 3; kh++) {
        int yy = y + kh - 1;
        if (yy < 0 || yy > 31) continue;
        for (int kw = 0; kw < 3; kw++) {
            int xx = x + kw - 1;
            if (xx < 0 || xx > 31) continue;
            #pragma unroll
            for (int ci = 0; ci < 8; ci++)
                s += w[((co*776 + 256 + ci)*3 + kh)*3 + kw] * spatial_val(ci, yy, xx);
        }
    }
    g_Sb[p * 256 + co] = s;
}

// ---------------- small fp32 NT GEMM (precompute only) ------------------------
template<int DO_BIAS, int DO_RELU>
__global__ void gemm_nt(const float* __restrict__ A, const float* __restrict__ B,
                        const float* __restrict__ bias,
                        float* __restrict__ C, int M, int Nn, int K) {
    __shared__ float As[16][64];
    __shared__ float Bs[16][64];
    const int bm = blockIdx.y * 64;
    const int bn = blockIdx.x * 64;
    const int tid = threadIdx.x;
    const int lr = tid >> 2;
    const int lc = (tid & 3) * 4;
    const int tm = (tid >> 4) * 4;
    const int tn = (tid & 15) * 4;

    float acc[4][4];
    #pragma unroll
    for (int i = 0; i < 4; i++)
        #pragma unroll
        for (int j = 0; j < 4; j++) acc[i][j] = 0.f;

    for (int k0 = 0; k0 < K; k0 += 16) {
        float4 av = make_float4(0,0,0,0), bv = make_float4(0,0,0,0);
        int kk = k0 + lc;
        int ar = bm + lr;
        if (ar < M) {
            if (kk + 4 <= K) av = *(const float4*)(A + (size_t)ar * K + kk);
            else { float* q = (float*)&av;
                   for (int j = 0; j < 4; j++) if (kk + j < K) q[j] = A[(size_t)ar * K + kk + j]; }
        }
        int br = bn + lr;
        if (br < Nn) {
            if (kk + 4 <= K) bv = *(const float4*)(B + (size_t)br * K + kk);
            else { float* q = (float*)&bv;
                   for (int j = 0; j < 4; j++) if (kk + j < K) q[j] = B[(size_t)br * K + kk + j]; }
        }
        As[lc+0][lr] = av.x; As[lc+1][lr] = av.y; As[lc+2][lr] = av.z; As[lc+3][lr] = av.w;
        Bs[lc+0][lr] = bv.x; Bs[lc+1][lr] = bv.y; Bs[lc+2][lr] = bv.z; Bs[lc+3][lr] = bv.w;
        __syncthreads();
        #pragma unroll
        for (int k = 0; k < 16; k++) {
            float a[4], b[4];
            #pragma unroll
            for (int i = 0; i < 4; i++) a[i] = As[k][tm + i];
            #pragma unroll
            for (int j = 0; j < 4; j++) b[j] = Bs[k][tn + j];
            #pragma unroll
            for (int i = 0; i < 4; i++)
                #pragma unroll
                for (int j = 0; j < 4; j++) acc[i][j] += a[i] * b[j];
        }
        __syncthreads();
    }

    #pragma unroll
    for (int i = 0; i < 4; i++) {
        int row = bm + tm + i;
        if (row >= M) continue;
        #pragma unroll
        for (int j = 0; j < 4; j++) {
            int col = bn + tn + j;
            float v = acc[i][j];
            if (DO_BIAS) v += bias[col];
            if (DO_RELU) v = fmaxf(v, 0.f);
            C[(size_t)row * Nn + col] = v;
        }
    }
}

// ============================================================================
// mma.sync split-bf16 GEMM core, fused products. CTA tile 128x128x32, 8 warps,
// warp tile 64x32. Dynamic smem: 2 buffers x 4 tiles (AH,AL,BH,BL), each tile
// [128][40] bf16 (10240B) -> 81920B/CTA. cp.async staging, occ 2.
// Per K-chunk: 3 compute passes (Ah*Bh, Ah*Bl, Al*Bh).
// ============================================================================

static constexpr int TILE_E = 128 * 40;        // elements per tile
static constexpr int MMA_SMEM_BYTES = 2 * 4 * TILE_E * 2;  // 81920

__device__ __forceinline__ void compute_tile(const __nv_bfloat16 (*sA)[40],
                                             const __nv_bfloat16 (*sB)[40],
                                             float acc[4][4][4], int wm, int wn, int lane) {
    const int r = lane & 7;
    const int t = lane >> 3;
    #pragma unroll
    for (int ks = 0; ks < 32; ks += 16) {
        uint32_t afr[4][4], bfr[4][2];
        #pragma unroll
        for (int mf = 0; mf < 4; mf++)
            ldsm4(afr[mf], &sA[wm + mf*16 + (t & 1)*8 + r][ks + (t >> 1)*8]);
        #pragma unroll
        for (int nf = 0; nf < 4; nf++)
            ldsm2(bfr[nf], &sB[wn + nf*8 + r][ks + (t & 1)*8]);
        #pragma unroll
        for (int mf = 0; mf < 4; mf++)
            #pragma unroll
            for (int nf = 0; nf < 4; nf++)
                mma16816(acc[mf][nf], afr[mf], bfr[nf]);
    }
}

// dense: A [M][K] bf16 hi/lo, B [Nn][K] bf16 hi/lo. grid = (Nn/128, M/128).
template<int RELU, int RES, int BF16OUT>
__global__ void __launch_bounds__(256, 2)
mma_dense(const __nv_bfloat16* __restrict__ Ah, const __nv_bfloat16* __restrict__ Al,
          const __nv_bfloat16* __restrict__ Bh, const __nv_bfloat16* __restrict__ Bl,
          int K, int ostride,
          const float* __restrict__ bias, const float* __restrict__ res,
          float* __restrict__ C, __nv_bfloat16* __restrict__ Ch, __nv_bfloat16* __restrict__ Cl) {
    extern __shared__ __align__(16) __nv_bfloat16 sm[];
    const uint32_t sm_base = (uint32_t)__cvta_generic_to_shared(sm);
    const int tid = threadIdx.x;
    const int lane = tid & 31, warp = tid >> 5;
    const int wm = (warp >> 2) * 64, wn = (warp & 3) * 32;
    const int bm = blockIdx.y * 128, bn = blockIdx.x * 128;
    const int r0 = tid >> 1, colh = (tid & 1) * 16;
    const uint32_t dst_off = (uint32_t)(r0 * 40 + colh) * 2;   // bytes within a tile

    float acc[4][4][4];
    #pragma unroll
    for (int i = 0; i < 4; i++)
        #pragma unroll
        for (int j = 0; j < 4; j++)
            #pragma unroll
            for (int q = 0; q < 4; q++) acc[i][j][q] = 0.f;

    const int nkc = K >> 5;

    auto fetch = [&](int kc, int buf) {
        int kpos = kc << 5;
        const __nv_bfloat16* a_h = Ah + (size_t)(bm + r0) * K + kpos + colh;
        const __nv_bfloat16* a_l = Al + (size_t)(bm + r0) * K + kpos + colh;
        const __nv_bfloat16* b_h = Bh + (size_t)(bn + r0) * K + kpos + colh;
        const __nv_bfloat16* b_l = Bl + (size_t)(bn + r0) * K + kpos + colh;
        uint32_t dAH = sm_base + (uint32_t)((buf*4 + 0) * TILE_E) * 2 + dst_off;
        uint32_t dAL = sm_base + (uint32_t)((buf*4 + 1) * TILE_E) * 2 + dst_off;
        uint32_t dBH = sm_base + (uint32_t)((buf*4 + 2) * TILE_E) * 2 + dst_off;
        uint32_t dBL = sm_base + (uint32_t)((buf*4 + 3) * TILE_E) * 2 + dst_off;
        cp16(dAH,      a_h,     16); cp16(dAH + 16, a_h + 8, 16);
        cp16(dAL,      a_l,     16); cp16(dAL + 16, a_l + 8, 16);
        cp16(dBH,      b_h,     16); cp16(dBH + 16, b_h + 8, 16);
        cp16(dBL,      b_l,     16); cp16(dBL + 16, b_l + 8, 16);
        cp_commit();
    };

    fetch(0, 0);
    cp_wait<0>(); __syncthreads();
    for (int kt = 0; kt < nkc; kt++) {
        const int cur = kt & 1;
        if (kt + 1 < nkc) fetch(kt + 1, cur ^ 1);
        const __nv_bfloat16 (*sAH)[40] = (const __nv_bfloat16(*)[40])(sm + (cur*4 + 0) * TILE_E);
        const __nv_bfloat16 (*sAL)[40] = (const __nv_bfloat16(*)[40])(sm + (cur*4 + 1) * TILE_E);
        const __nv_bfloat16 (*sBH)[40] = (const __nv_bfloat16(*)[40])(sm + (cur*4 + 2) * TILE_E);
        const __nv_bfloat16 (*sBL)[40] = (const __nv_bfloat16(*)[40])(sm + (cur*4 + 3) * TILE_E);
        compute_tile(sAH, sBH, acc, wm, wn, lane);
        compute_tile(sAH, sBL, acc, wm, wn, lane);
        compute_tile(sAL, sBH, acc, wm, wn, lane);
        if (kt + 1 < nkc) cp_wait<0>();
        __syncthreads();
    }

    const int group = lane >> 2, tig = lane & 3;
    #pragma unroll
    for (int mf = 0; mf < 4; mf++)
        #pragma unroll
        for (int nf = 0; nf < 4; nf++) {
            int col = bn + wn + nf*8 + tig*2;
            #pragma unroll
            for (int h2 = 0; h2 < 2; h2++) {
                int row = bm + wm + mf*16 + group + h2*8;
                float v0 = acc[mf][nf][h2*2+0] + bias[col];
                float v1 = acc[mf][nf][h2*2+1] + bias[col+1];
                if (RES) {
                    v0 += res[(size_t)row * 256 + col];
                    v1 += res[(size_t)row * 256 + col + 1];
                }
                if (RELU) { v0 = fmaxf(v0, 0.f); v1 = fmaxf(v1, 0.f); }
                if (BF16OUT) {
                    __nv_bfloat16 h, l;
                    split_bf16(v0, h, l);
                    Ch[(size_t)row * 256 + col] = h; Cl[(size_t)row * 256 + col] = l;
                    split_bf16(v1, h, l);
                    Ch[(size_t)row * 256 + col + 1] = h; Cl[(size_t)row * 256 + col + 1] = l;
                } else {
                    *(float2*)(C + (size_t)row * ostride + col) = make_float2(v0, v1);
                }
            }
        }
}

// conv: implicit GEMM, A gathered from g_fb_{h,l} (K=2304, tap-major),
// B = g_bd_{h,l}. Epilogue +Sb +Hb, relu -> g_t. grid = (2, 128).
__global__ void __launch_bounds__(256, 2)
mma_conv() {
    extern __shared__ __align__(16) __nv_bfloat16 sm[];
    const uint32_t sm_base = (uint32_t)__cvta_generic_to_shared(sm);
    const int tid = threadIdx.x;
    const int lane = tid & 31, warp = tid >> 5;
    const int wm = (warp >> 2) * 64, wn = (warp & 3) * 32;
    const int bm = blockIdx.y * 128, bn = blockIdx.x * 128;
    const int r0 = tid >> 1, colh = (tid & 1) * 16;
    const uint32_t dst_off = (uint32_t)(r0 * 40 + colh) * 2;

    // this thread's A row geometry (fixed across iterations)
    const int arow = bm + r0;
    const int an = arow >> 10, ap_ = arow & 1023;
    const int ay = ap_ >> 5, ax = ap_ & 31;

    float acc[4][4][4];
    #pragma unroll
    for (int i = 0; i < 4; i++)
        #pragma unroll
        for (int j = 0; j < 4; j++)
            #pragma unroll
            for (int q = 0; q < 4; q++) acc[i][j][q] = 0.f;

    const int nkc = 72;           // 2304/32

    auto fetch = [&](int kc, int buf) {
        int kpos = kc << 5;
        int tap  = kc >> 3;              // 8 chunks of 32 per 256-wide tap
        int ci   = (kpos & 255) + colh;
        int dy = tap / 3 - 1;
        int dx = tap % 3 - 1;
        int yy = ay + dy, xx = ax + dx;
        bool ok = (yy >= 0 && yy < 32 && xx >= 0 && xx < 32);
        int sz = ok ? 16 : 0;
        size_t abase = ok ? ((size_t)((an << 10) + (yy << 5) + xx) * 256 + ci) : 0;
        const __nv_bfloat16* a_h = g_fb_h + abase;
        const __nv_bfloat16* a_l = g_fb_l + abase;
        const __nv_bfloat16* b_h = g_bd_h + (size_t)(bn + r0) * 2304 + kpos + colh;
        const __nv_bfloat16* b_l = g_bd_l + (size_t)(bn + r0) * 2304 + kpos + colh;
        uint32_t dAH = sm_base + (uint32_t)((buf*4 + 0) * TILE_E) * 2 + dst_off;
        uint32_t dAL = sm_base + (uint32_t)((buf*4 + 1) * TILE_E) * 2 + dst_off;
        uint32_t dBH = sm_base + (uint32_t)((buf*4 + 2) * TILE_E) * 2 + dst_off;
        uint32_t dBL = sm_base + (uint32_t)((buf*4 + 3) * TILE_E) * 2 + dst_off;
        cp16(dAH,      a_h,     sz); cp16(dAH + 16, a_h + 8, sz);
        cp16(dAL,      a_l,     sz); cp16(dAL + 16, a_l + 8, sz);
        cp16(dBH,      b_h,     16); cp16(dBH + 16, b_h + 8, 16);
        cp16(dBL,      b_l,     16); cp16(dBL + 16, b_l + 8, 16);
        cp_commit();
    };

    fetch(0, 0);
    cp_wait<0>(); __syncthreads();
    for (int kt = 0; kt < nkc; kt++) {
        const int cur = kt & 1;
        if (kt + 1 < nkc) fetch(kt + 1, cur ^ 1);
        const __nv_bfloat16 (*sAH)[40] = (const __nv_bfloat16(*)[40])(sm + (cur*4 + 0) * TILE_E);
        const __nv_bfloat16 (*sAL)[40] = (const __nv_bfloat16(*)[40])(sm + (cur*4 + 1) * TILE_E);
        const __nv_bfloat16 (*sBH)[40] = (const __nv_bfloat16(*)[40])(sm + (cur*4 + 2) * TILE_E);
        const __nv_bfloat16 (*sBL)[40] = (const __nv_bfloat16(*)[40])(sm + (cur*4 + 3) * TILE_E);
        compute_tile(sAH, sBH, acc, wm, wn, lane);
        compute_tile(sAH, sBL, acc, wm, wn, lane);
        compute_tile(sAL, sBH, acc, wm, wn, lane);
        if (kt + 1 < nkc) cp_wait<0>();
        __syncthreads();
    }

    const int group = lane >> 2, tig = lane & 3;
    #pragma unroll
    for (int mf = 0; mf < 4; mf++)
        #pragma unroll
        for (int nf = 0; nf < 4; nf++) {
            int col = bn + wn + nf*8 + tig*2;
            #pragma unroll
            for (int h2 = 0; h2 < 2; h2++) {
                int row = bm + wm + mf*16 + group + h2*8;
                int n2 = row >> 10, p2 = row & 1023;
                int y2 = p2 >> 5, x2 = p2 & 31;
                int ty = (y2 == 0) ? 0 : ((y2 == 31) ? 2 : 1);
                int tx = (x2 == 0) ? 0 : ((x2 == 31) ? 2 : 1);
                const float* Hrow = g_Hb + (n2 * 9 + ty * 3 + tx) * 256;
                const float* Srow = g_Sb + p2 * 256;
                float v0 = fmaxf(acc[mf][nf][h2*2+0] + Srow[col]   + Hrow[col],   0.f);
                float v1 = fmaxf(acc[mf][nf][h2*2+1] + Srow[col+1] + Hrow[col+1], 0.f);
                *(float2*)(g_t + (size_t)row * 256 + col) = make_float2(v0, v1);
            }
        }
}

// ---------------- layernorm (warp per row); writes fp32 + bf16 hi/lo ---------
__global__ void ln_split(const float* __restrict__ X, const float* __restrict__ g,
                         const float* __restrict__ b, float* __restrict__ Y,
                         __nv_bfloat16* __restrict__ Yh, __nv_bfloat16* __restrict__ Yl) {
    int warp = (blockIdx.x * blockDim.x + threadIdx.x) >> 5;
    int lane = threadIdx.x & 31;
    if (warp >= 16384) return;
    const float* xr = X + (size_t)warp * 256;
    float v[8], s = 0.f, s2 = 0.f;
    #pragma unroll
    for (int j = 0; j < 8; j++) {
        v[j] = xr[j * 32 + lane];
        s += v[j]; s2 += v[j] * v[j];
    }
    #pragma unroll
    for (int o = 16; o > 0; o >>= 1) {
        s  += __shfl_xor_sync(0xffffffffu, s, o);
        s2 += __shfl_xor_sync(0xffffffffu, s2, o);
    }
    float mean = s * (1.f / 256.f);
    float var  = s2 * (1.f / 256.f) - mean * mean;
    float inv  = rsqrtf(var + 1e-5f);
    #pragma unroll
    for (int j = 0; j < 8; j++) {
        int c = j * 32 + lane;
        float y = (v[j] - mean) * inv * g[c] + b[c];
        size_t o = (size_t)warp * 256 + c;
        Y[o] = y;
        __nv_bfloat16 h, l; split_bf16(y, h, l);
        Yh[o] = h; Yl[o] = l;
    }
}

// final LN + gated commit: writes feat bf16 hi/lo + dout NCHW
__global__ void ln_gate(const float* __restrict__ X, const float* __restrict__ g,
                        const float* __restrict__ b, const int* __restrict__ words,
                        int s, float* __restrict__ dout) {
    if (words[s] == 0) return;
    int warp = (blockIdx.x * blockDim.x + threadIdx.x) >> 5;
    int lane = threadIdx.x & 31;
    if (warp >= 16384) return;
    const float* xr = X + (size_t)warp * 256;
    float v[8], sm = 0.f, s2 = 0.f;
    #pragma unroll
    for (int j = 0; j < 8; j++) {
        v[j] = xr[j * 32 + lane];
        sm += v[j]; s2 += v[j] * v[j];
    }
    #pragma unroll
    for (int o = 16; o > 0; o >>= 1) {
        sm += __shfl_xor_sync(0xffffffffu, sm, o);
        s2 += __shfl_xor_sync(0xffffffffu, s2, o);
    }
    float mean = sm * (1.f / 256.f);
    float var  = s2 * (1.f / 256.f) - mean * mean;
    float inv  = rsqrtf(var + 1e-5f);
    int n = warp >> 10, p = warp & 1023;
    #pragma unroll
    for (int j = 0; j < 8; j++) {
        int c = j * 32 + lane;
        float y = (v[j] - mean) * inv * g[c] + b[c];
        size_t o = (size_t)warp * 256 + c;
        __nv_bfloat16 h, l; split_bf16(y, h, l);
        g_fb_h[o] = h; g_fb_l[o] = l;
        dout[(size_t)n * 262144 + (size_t)c * 1024 + p] = y;
    }
}

// ---------------- cross-batch attention per (position, head) -----------------
__global__ void attn_kernel(int s) {
    const int p = blockIdx.x;
    const int h = blockIdx.y;
    __shared__ float qs[16][128];
    __shared__ float ks[16][129];
    __shared__ float vs[16][129];
    __shared__ float sc[16][16];
    const int tid = threadIdx.x;

    for (int i = tid; i < 16 * 128; i += 256) {
        int m = i >> 7, d = i & 127;
        qs[m][d] = g_qh[(size_t)(m * 20 + s) * 256 + h * 128 + d];
        const float* kvp = g_kv + (size_t)((m << 10) + p) * 512 + h * 128 + d;
        ks[m][d] = kvp[0];
        vs[m][d] = kvp[256];
    }
    __syncthreads();
    {
        int l = tid >> 4, m = tid & 15;
        float dot = 0.f;
        #pragma unroll
        for (int d = 0; d < 128; d++) dot += qs[l][d] * ks[m][d];
        sc[l][m] = dot * 0.08838834764831845f;
    }
    __syncthreads();
    if (tid < 16) {
        float mx = -1e30f;
        #pragma unroll
        for (int m = 0; m < 16; m++) mx = fmaxf(mx, sc[tid][m]);
        float sum = 0.f;
        #pragma unroll
        for (int m = 0; m < 16; m++) { float e = expf(sc[tid][m] - mx); sc[tid][m] = e; sum += e; }
        float inv = 1.f / sum;
        #pragma unroll
        for (int m = 0; m < 16; m++) sc[tid][m] *= inv;
    }
    __syncthreads();
    for (int i = tid; i < 16 * 128; i += 256) {
        int l = i >> 7, d = i & 127;
        float o = 0.f;
        #pragma unroll
        for (int m = 0; m < 16; m++) o += sc[l][m] * vs[m][d];
        size_t oidx = (size_t)((l << 10) + p) * 256 + h * 128 + d;
        __nv_bfloat16 hh, ll; split_bf16(o, hh, ll);
        g_ob_h[oidx] = hh; g_ob_l[oidx] = ll;
    }
}

// ============================================================================
// launch
// ============================================================================
extern "C" void kernel_launch(void* const* d_in, const int* in_sizes, int n_in,
                              void* d_out, int out_size) {
    (void)in_sizes; (void)n_in; (void)out_size;
    const float* hn        = (const float*)d_in[1];
    const float* feature   = (const float*)d_in[2];
    const float* embedding = (const float*)d_in[3];
    const int*   words     = (const int*)  d_in[4];
    const float* qconv_w   = (const float*)d_in[5];
    const float* qconv_b   = (const float*)d_in[6];
    const float* mconv_w   = (const float*)d_in[7];
    const float* mnorm_g   = (const float*)d_in[8];
    const float* mnorm_b   = (const float*)d_in[9];
    const float* in_proj_w = (const float*)d_in[10];
    const float* in_proj_b = (const float*)d_in[11];
    const float* out_proj_w= (const float*)d_in[12];
    const float* out_proj_b= (const float*)d_in[13];
    const float* norm_g    = (const float*)d_in[14];
    const float* norm_b    = (const float*)d_in[15];
    const float* lin1_w    = (const float*)d_in[16];
    const float* lin1_b    = (const float*)d_in[17];
    const float* lin2_w    = (const float*)d_in[18];
    const float* lin2_b    = (const float*)d_in[19];
    const float* normf_g   = (const float*)d_in[20];
    const float* normf_b   = (const float*)d_in[21];
    float* dout = (float*)d_out;

    float *p_t, *p_tln, *p_kv, *p_x1, *p_fea, *p_x2, *p_qt, *p_qh;
    __nv_bfloat16 *p_tlnh, *p_tlnl, *p_obh, *p_obl, *p_feah, *p_feal, *p_h1h, *p_h1l;
    __nv_bfloat16 *p_wih, *p_wil, *p_woh, *p_wol, *p_w1h, *p_w1l, *p_w2h, *p_w2l;
    cudaGetSymbolAddress((void**)&p_t,    g_t);
    cudaGetSymbolAddress((void**)&p_tln,  g_tln);
    cudaGetSymbolAddress((void**)&p_kv,   g_kv);
    cudaGetSymbolAddress((void**)&p_x1,   g_x1);
    cudaGetSymbolAddress((void**)&p_fea,  g_fea);
    cudaGetSymbolAddress((void**)&p_x2,   g_x2);
    cudaGetSymbolAddress((void**)&p_qt,   g_qt);
    cudaGetSymbolAddress((void**)&p_qh,   g_qh);
    cudaGetSymbolAddress((void**)&p_tlnh, g_tln_h);
    cudaGetSymbolAddress((void**)&p_tlnl, g_tln_l);
    cudaGetSymbolAddress((void**)&p_obh,  g_ob_h);
    cudaGetSymbolAddress((void**)&p_obl,  g_ob_l);
    cudaGetSymbolAddress((void**)&p_feah, g_fea_h);
    cudaGetSymbolAddress((void**)&p_feal, g_fea_l);
    cudaGetSymbolAddress((void**)&p_h1h,  g_h1_h);
    cudaGetSymbolAddress((void**)&p_h1l,  g_h1_l);
    cudaGetSymbolAddress((void**)&p_wih,  g_wi_h);
    cudaGetSymbolAddress((void**)&p_wil,  g_wi_l);
    cudaGetSymbolAddress((void**)&p_woh,  g_wo_h);
    cudaGetSymbolAddress((void**)&p_wol,  g_wo_l);
    cudaGetSymbolAddress((void**)&p_w1h,  g_w1_h);
    cudaGetSymbolAddress((void**)&p_w1l,  g_w1_l);
    cudaGetSymbolAddress((void**)&p_w2h,  g_w2_h);
    cudaGetSymbolAddress((void**)&p_w2l,  g_w2_l);

    cudaFuncSetAttribute(mma_dense<0,0,0>, cudaFuncAttributeMaxDynamicSharedMemorySize, MMA_SMEM_BYTES);
    cudaFuncSetAttribute(mma_dense<0,1,0>, cudaFuncAttributeMaxDynamicSharedMemorySize, MMA_SMEM_BYTES);
    cudaFuncSetAttribute(mma_dense<1,0,1>, cudaFuncAttributeMaxDynamicSharedMemorySize, MMA_SMEM_BYTES);
    cudaFuncSetAttribute(mma_conv,         cudaFuncAttributeMaxDynamicSharedMemorySize, MMA_SMEM_BYTES);

    const int T = 256;

    // ---- step-invariant precompute ----
    k_init_feat<<<DIV_UP(16*256*1024, T), T>>>(feature, dout);
    k_repack   <<<DIV_UP(256*2304,   T), T>>>(mconv_w);
    k_wsum     <<<DIV_UP(9*512*256,  T), T>>>(mconv_w);
    k_hb       <<<DIV_UP(16*9*256,   T), T>>>(hn);
    k_sb       <<<DIV_UP(1024*256,   T), T>>>(mconv_w);
    k_split<<<DIV_UP(768*256, T), T>>>(in_proj_w,  p_wih, p_wil, 768*256);
    k_split<<<DIV_UP(256*256, T), T>>>(out_proj_w, p_woh, p_wol, 256*256);
    k_split<<<DIV_UP(256*256, T), T>>>(lin1_w,     p_w1h, p_w1l, 256*256);
    k_split<<<DIV_UP(256*256, T), T>>>(lin2_w,     p_w2h, p_w2l, 256*256);
    gemm_nt<1,1><<<dim3(4,5), T>>>(embedding, qconv_w, qconv_b, p_qt, 320, 256, 300);
    gemm_nt<1,0><<<dim3(4,5), T>>>(p_qt, in_proj_w, in_proj_b, p_qh, 320, 256, 256);

    // ---- sequence loop ----
    for (int s = 0; s < 20; s++) {
        mma_conv<<<dim3(2, 128), T, MMA_SMEM_BYTES>>>();
        ln_split<<<2048, T>>>(p_t, mnorm_g, mnorm_b, p_tln, p_tlnh, p_tlnl);
        // fused K|V projection: rows 256..767 of in_proj, Nn=512
        mma_dense<0,0,0><<<dim3(4, 128), T, MMA_SMEM_BYTES>>>(
            p_tlnh, p_tlnl, p_wih + 256*256, p_wil + 256*256,
            256, 512, in_proj_b + 256, nullptr, p_kv, nullptr, nullptr);
        attn_kernel<<<dim3(1024, 2), T>>>(s);
        mma_dense<0,1,0><<<dim3(2, 128), T, MMA_SMEM_BYTES>>>(
            p_obh, p_obl, p_woh, p_wol,
            256, 256, out_proj_b, p_tln, p_x1, nullptr, nullptr);
        ln_split<<<2048, T>>>(p_x1, norm_g, norm_b, p_fea, p_feah, p_feal);
        mma_dense<1,0,1><<<dim3(2, 128), T, MMA_SMEM_BYTES>>>(
            p_feah, p_feal, p_w1h, p_w1l,
            256, 256, lin1_b, nullptr, nullptr, p_h1h, p_h1l);
        mma_dense<0,1,0><<<dim3(2, 128), T, MMA_SMEM_BYTES>>>(
            p_h1h, p_h1l, p_w2h, p_w2l,
            256, 256, lin2_b, p_fea, p_x2, nullptr, nullptr);
        ln_gate<<<2048, T>>>(p_x2, normf_g, normf_b, words, s, dout);
    }
}

// round 12
// speedup vs baseline: 1.2922x; 1.2922x over previous
#include <cuda_runtime.h>
#include <cuda_bf16.h>
#include <math.h>
#include <stdint.h>

// ============================================================================
// N=16, SEQ=20, P=32*32=1024, VD=256, HN=512, EMB=300, NHEAD=2, DH=128
// conv input channels: feat 0..255, spatial 256..263, hn 264..775
// Split-bf16 GEMM on mma.sync (HMMA): C = Ah*Bh + Ah*Bl + Al*Bh  (~1e-5 err)
// R11: revert to R8 structure (best: 10764us); hoist dout write out of the
// step loop (per-step NCHW scatter was ~8x write-amplified dead work).
// ============================================================================

#define DIV_UP(a,b) (((a)+(b)-1)/(b))

__device__ __forceinline__ void split_bf16(float v, __nv_bfloat16& h, __nv_bfloat16& l) {
    h = __float2bfloat16(v);
    l = __float2bfloat16(v - __bfloat162float(h));
}

__device__ __forceinline__ void ldsm4(uint32_t* d, const void* p) {
    uint32_t addr = (uint32_t)__cvta_generic_to_shared(p);
    asm volatile("ldmatrix.sync.aligned.m8n8.x4.shared.b16 {%0,%1,%2,%3}, [%4];"
        : "=r"(d[0]), "=r"(d[1]), "=r"(d[2]), "=r"(d[3]) : "r"(addr));
}
__device__ __forceinline__ void ldsm2(uint32_t* d, const void* p) {
    uint32_t addr = (uint32_t)__cvta_generic_to_shared(p);
    asm volatile("ldmatrix.sync.aligned.m8n8.x2.shared.b16 {%0,%1}, [%2];"
        : "=r"(d[0]), "=r"(d[1]) : "r"(addr));
}
__device__ __forceinline__ void mma16816(float* c, const uint32_t* a, const uint32_t* b) {
    asm volatile("mma.sync.aligned.m16n8k16.row.col.f32.bf16.bf16.f32 "
        "{%0,%1,%2,%3}, {%4,%5,%6,%7}, {%8,%9}, {%0,%1,%2,%3};"
        : "+f"(c[0]), "+f"(c[1]), "+f"(c[2]), "+f"(c[3])
        : "r"(a[0]), "r"(a[1]), "r"(a[2]), "r"(a[3]), "r"(b[0]), "r"(b[1]));
}

// ---------------- scratch (device globals) -----------------------------------
__device__ __nv_bfloat16 g_fb_h [16*1024*256], g_fb_l [16*1024*256];  // feat (n,p,c)
__device__ __nv_bfloat16 g_tln_h[16384*256],   g_tln_l[16384*256];
__device__ __nv_bfloat16 g_ob_h [16384*256],   g_ob_l [16384*256];
__device__ __nv_bfloat16 g_fea_h[16384*256],   g_fea_l[16384*256];
__device__ __nv_bfloat16 g_h1_h [16384*256],   g_h1_l [16384*256];
__device__ __nv_bfloat16 g_wi_h [768*256],     g_wi_l [768*256];      // in_proj
__device__ __nv_bfloat16 g_wo_h [256*256],     g_wo_l [256*256];
__device__ __nv_bfloat16 g_w1_h [256*256],     g_w1_l [256*256];
__device__ __nv_bfloat16 g_w2_h [256*256],     g_w2_l [256*256];
__device__ __nv_bfloat16 g_bd_h [256*2304],    g_bd_l [256*2304];     // conv weights
__device__ float g_t   [16384*256];
__device__ float g_tln [16384*256];
__device__ float g_kv  [16384*512];
__device__ float g_x1  [16384*256];
__device__ float g_fea [16384*256];
__device__ float g_x2  [16384*256];
__device__ float g_Wsum[9*512*256];
__device__ float g_Hb  [16*9*256];
__device__ float g_Sb  [1024*256];
__device__ float g_qt  [320*256];
__device__ float g_qh  [320*256];

// ---------------- init / precompute ------------------------------------------
__global__ void k_init_feat(const float* __restrict__ feature, float* __restrict__ dout) {
    int idx = blockIdx.x * blockDim.x + threadIdx.x;   // NCHW linear
    if (idx >= 16*256*1024) return;
    int n = idx >> 18;
    int r = idx & 262143;
    int c = r >> 10;
    int p = r & 1023;
    float v = feature[idx];
    dout[idx] = v;
    __nv_bfloat16 h, l; split_bf16(v, h, l);
    size_t o = (size_t)((n << 10) + p) * 256 + c;
    g_fb_h[o] = h; g_fb_l[o] = l;
}

__global__ void k_repack(const float* __restrict__ w) {
    int idx = blockIdx.x * blockDim.x + threadIdx.x;
    if (idx >= 256*2304) return;
    int co  = idx / 2304;
    int k   = idx % 2304;
    int tap = k >> 8;
    int ci  = k & 255;
    int kh = tap / 3, kw = tap % 3;
    float v = w[((co*776 + ci)*3 + kh)*3 + kw];
    __nv_bfloat16 h, l; split_bf16(v, h, l);
    g_bd_h[idx] = h; g_bd_l[idx] = l;
}

__global__ void k_split(const float* __restrict__ src, __nv_bfloat16* __restrict__ h,
                        __nv_bfloat16* __restrict__ l, int n) {
    int i = blockIdx.x * blockDim.x + threadIdx.x;
    if (i >= n) return;
    __nv_bfloat16 hh, ll; split_bf16(src[i], hh, ll);
    h[i] = hh; l[i] = ll;
}

__global__ void k_wsum(const float* __restrict__ w) {
    int idx = blockIdx.x * blockDim.x + threadIdx.x;
    if (idx >= 9*512*256) return;
    int co   = idx & 255;
    int tmp  = idx >> 8;
    int ci   = tmp & 511;
    int type = tmp >> 9;
    int ty = type / 3, tx = type % 3;
    int kh0 = (ty == 0) ? 1 : 0, kh1 = (ty == 2) ? 1 : 2;
    int kw0 = (tx == 0) ? 1 : 0, kw1 = (tx == 2) ? 1 : 2;
    float s = 0.f;
    for (int kh = kh0; kh <= kh1; kh++)
        for (int kw = kw0; kw <= kw1; kw++)
            s += w[((co*776 + 264 + ci)*3 + kh)*3 + kw];
    g_Wsum[idx] = s;
}

__global__ void k_hb(const float* __restrict__ hn) {
    int idx = blockIdx.x * blockDim.x + threadIdx.x;
    if (idx >= 16*9*256) return;
    int co   = idx & 255;
    int type = (idx >> 8) % 9;
    int n    = idx / 2304;
    const float* hr = hn + n * 512;
    const float* wr = g_Wsum + type * 512 * 256 + co;
    float s = 0.f;
    for (int ci = 0; ci < 512; ci++) s += hr[ci] * wr[ci * 256];
    g_Hb[idx] = s;
}

__device__ __forceinline__ float spatial_val(int ci, int yy, int xx) {
    const float inv = 1.f / 32.f;
    switch (ci) {
        case 0: return xx * (2.f*inv) - 1.f;
        case 1: return yy * (2.f*inv) - 1.f;
        case 2: return (xx + 1) * (2.f*inv) - 1.f;
        case 3: return (yy + 1) * (2.f*inv) - 1.f;
        case 4: return (xx + 0.5f) * (2.f*inv) - 1.f;
        case 5: return (yy + 0.5f) * (2.f*inv) - 1.f;
        default: return inv;
    }
}

__global__ void k_sb(const float* __restrict__ w) {
    int idx = blockIdx.x * blockDim.x + threadIdx.x;
    if (idx >= 1024*256) return;
    int co = idx & 255;
    int p  = idx >> 8;
    int y = p >> 5, x = p & 31;
    float s = 0.f;
    for (int kh = 0; kh < 3; kh++) {
        int yy = y + kh - 1;
        if (yy < 0 || yy > 31) continue;
        for (int kw = 0; kw < 3; kw++) {
            int xx = x + kw - 1;
            if (xx < 0 || xx > 31) continue;
            #pragma unroll
            for (int ci = 0; ci < 8; ci++)
                s += w[((co*776 + 256 + ci)*3 + kh)*3 + kw] * spatial_val(ci, yy, xx);
        }
    }
    g_Sb[p * 256 + co] = s;
}

// ---------------- small fp32 NT GEMM (precompute only) ------------------------
template<int DO_BIAS, int DO_RELU>
__global__ void gemm_nt(const float* __restrict__ A, const float* __restrict__ B,
                        const float* __restrict__ bias,
                        float* __restrict__ C, int M, int Nn, int K) {
    __shared__ float As[16][64];
    __shared__ float Bs[16][64];
    const int bm = blockIdx.y * 64;
    const int bn = blockIdx.x * 64;
    const int tid = threadIdx.x;
    const int lr = tid >> 2;
    const int lc = (tid & 3) * 4;
    const int tm = (tid >> 4) * 4;
    const int tn = (tid & 15) * 4;

    float acc[4][4];
    #pragma unroll
    for (int i = 0; i < 4; i++)
        #pragma unroll
        for (int j = 0; j < 4; j++) acc[i][j] = 0.f;

    for (int k0 = 0; k0 < K; k0 += 16) {
        float4 av = make_float4(0,0,0,0), bv = make_float4(0,0,0,0);
        int kk = k0 + lc;
        int ar = bm + lr;
        if (ar < M) {
            if (kk + 4 <= K) av = *(const float4*)(A + (size_t)ar * K + kk);
            else { float* q = (float*)&av;
                   for (int j = 0; j < 4; j++) if (kk + j < K) q[j] = A[(size_t)ar * K + kk + j]; }
        }
        int br = bn + lr;
        if (br < Nn) {
            if (kk + 4 <= K) bv = *(const float4*)(B + (size_t)br * K + kk);
            else { float* q = (float*)&bv;
                   for (int j = 0; j < 4; j++) if (kk + j < K) q[j] = B[(size_t)br * K + kk + j]; }
        }
        As[lc+0][lr] = av.x; As[lc+1][lr] = av.y; As[lc+2][lr] = av.z; As[lc+3][lr] = av.w;
        Bs[lc+0][lr] = bv.x; Bs[lc+1][lr] = bv.y; Bs[lc+2][lr] = bv.z; Bs[lc+3][lr] = bv.w;
        __syncthreads();
        #pragma unroll
        for (int k = 0; k < 16; k++) {
            float a[4], b[4];
            #pragma unroll
            for (int i = 0; i < 4; i++) a[i] = As[k][tm + i];
            #pragma unroll
            for (int j = 0; j < 4; j++) b[j] = Bs[k][tn + j];
            #pragma unroll
            for (int i = 0; i < 4; i++)
                #pragma unroll
                for (int j = 0; j < 4; j++) acc[i][j] += a[i] * b[j];
        }
        __syncthreads();
    }

    #pragma unroll
    for (int i = 0; i < 4; i++) {
        int row = bm + tm + i;
        if (row >= M) continue;
        #pragma unroll
        for (int j = 0; j < 4; j++) {
            int col = bn + tn + j;
            float v = acc[i][j];
            if (DO_BIAS) v += bias[col];
            if (DO_RELU) v = fmaxf(v, 0.f);
            C[(size_t)row * Nn + col] = v;
        }
    }
}

// ============================================================================
// mma.sync split-bf16 GEMM core (R8 structure). CTA tile 128x128x32, 8 warps,
// warp tile 64x32. smem [128][40] padded; 3 sequential product passes over K;
// register-prefetch double buffering; __launch_bounds__(256,2).
// ============================================================================

__device__ __forceinline__ void compute_tile(const __nv_bfloat16 (*sA)[40],
                                             const __nv_bfloat16 (*sB)[40],
                                             float acc[4][4][4], int wm, int wn, int lane) {
    const int r = lane & 7;
    const int t = lane >> 3;
    #pragma unroll
    for (int ks = 0; ks < 32; ks += 16) {
        uint32_t afr[4][4], bfr[4][2];
        #pragma unroll
        for (int mf = 0; mf < 4; mf++)
            ldsm4(afr[mf], &sA[wm + mf*16 + (t & 1)*8 + r][ks + (t >> 1)*8]);
        #pragma unroll
        for (int nf = 0; nf < 4; nf++)
            ldsm2(bfr[nf], &sB[wn + nf*8 + r][ks + (t & 1)*8]);
        #pragma unroll
        for (int mf = 0; mf < 4; mf++)
            #pragma unroll
            for (int nf = 0; nf < 4; nf++)
                mma16816(acc[mf][nf], afr[mf], bfr[nf]);
    }
}

// dense: A [M][K] bf16 hi/lo, B [Nn][K] bf16 hi/lo. grid = (Nn/128, M/128).
template<int RELU, int RES, int BF16OUT>
__global__ void __launch_bounds__(256, 2)
mma_dense(const __nv_bfloat16* __restrict__ Ah, const __nv_bfloat16* __restrict__ Al,
          const __nv_bfloat16* __restrict__ Bh, const __nv_bfloat16* __restrict__ Bl,
          int K, int ostride,
          const float* __restrict__ bias, const float* __restrict__ res,
          float* __restrict__ C, __nv_bfloat16* __restrict__ Ch, __nv_bfloat16* __restrict__ Cl) {
    __shared__ __align__(16) __nv_bfloat16 sA[2][128][40];
    __shared__ __align__(16) __nv_bfloat16 sB[2][128][40];
    const int tid = threadIdx.x;
    const int lane = tid & 31, warp = tid >> 5;
    const int wm = (warp >> 2) * 64, wn = (warp & 3) * 32;
    const int bm = blockIdx.y * 128, bn = blockIdx.x * 128;
    const int r0 = tid >> 1, colh = (tid & 1) * 16;

    float acc[4][4][4];
    #pragma unroll
    for (int i = 0; i < 4; i++)
        #pragma unroll
        for (int j = 0; j < 4; j++)
            #pragma unroll
            for (int q = 0; q < 4; q++) acc[i][j][q] = 0.f;

    const int nkc = K >> 5;
    const int nit = 3 * nkc;
    uint4 ra0, ra1, rb0, rb1;

    auto fetch = [&](int it) {
        int prod = (it < nkc) ? 0 : ((it < 2*nkc) ? 1 : 2);
        int kpos = (it - prod * nkc) << 5;
        const __nv_bfloat16* As = (prod < 2) ? Ah : Al;
        const __nv_bfloat16* Bs = (prod == 1) ? Bl : Bh;
        const __nv_bfloat16* ap = As + (size_t)(bm + r0) * K + kpos + colh;
        const __nv_bfloat16* bp = Bs + (size_t)(bn + r0) * K + kpos + colh;
        ra0 = *(const uint4*)(ap);
        ra1 = *(const uint4*)(ap + 8);
        rb0 = *(const uint4*)(bp);
        rb1 = *(const uint4*)(bp + 8);
    };
    auto put = [&](int buf) {
        *(uint4*)&sA[buf][r0][colh]     = ra0;
        *(uint4*)&sA[buf][r0][colh + 8] = ra1;
        *(uint4*)&sB[buf][r0][colh]     = rb0;
        *(uint4*)&sB[buf][r0][colh + 8] = rb1;
    };

    fetch(0); put(0); __syncthreads();
    for (int it = 0; it < nit; it++) {
        int cur = it & 1;
        if (it + 1 < nit) fetch(it + 1);
        compute_tile(sA[cur], sB[cur], acc, wm, wn, lane);
        if (it + 1 < nit) put(cur ^ 1);
        __syncthreads();
    }

    const int group = lane >> 2, tig = lane & 3;
    #pragma unroll
    for (int mf = 0; mf < 4; mf++)
        #pragma unroll
        for (int nf = 0; nf < 4; nf++) {
            int col = bn + wn + nf*8 + tig*2;
            #pragma unroll
            for (int h2 = 0; h2 < 2; h2++) {
                int row = bm + wm + mf*16 + group + h2*8;
                float v0 = acc[mf][nf][h2*2+0] + bias[col];
                float v1 = acc[mf][nf][h2*2+1] + bias[col+1];
                if (RES) {
                    v0 += res[(size_t)row * 256 + col];
                    v1 += res[(size_t)row * 256 + col + 1];
                }
                if (RELU) { v0 = fmaxf(v0, 0.f); v1 = fmaxf(v1, 0.f); }
                if (BF16OUT) {
                    __nv_bfloat16 h, l;
                    split_bf16(v0, h, l);
                    Ch[(size_t)row * 256 + col] = h; Cl[(size_t)row * 256 + col] = l;
                    split_bf16(v1, h, l);
                    Ch[(size_t)row * 256 + col + 1] = h; Cl[(size_t)row * 256 + col + 1] = l;
                } else {
                    *(float2*)(C + (size_t)row * ostride + col) = make_float2(v0, v1);
                }
            }
        }
}

// conv: implicit GEMM, A gathered from g_fb_{h,l} (K=2304, tap-major),
// B = g_bd_{h,l}. Epilogue +Sb +Hb, relu -> g_t. grid = (2, 128).
__global__ void __launch_bounds__(256, 2)
mma_conv() {
    __shared__ __align__(16) __nv_bfloat16 sA[2][128][40];
    __shared__ __align__(16) __nv_bfloat16 sB[2][128][40];
    const int tid = threadIdx.x;
    const int lane = tid & 31, warp = tid >> 5;
    const int wm = (warp >> 2) * 64, wn = (warp & 3) * 32;
    const int bm = blockIdx.y * 128, bn = blockIdx.x * 128;
    const int r0 = tid >> 1, colh = (tid & 1) * 16;

    // this thread's A row geometry (fixed across iterations)
    const int arow = bm + r0;
    const int an = arow >> 10, ap_ = arow & 1023;
    const int ay = ap_ >> 5, ax = ap_ & 31;

    float acc[4][4][4];
    #pragma unroll
    for (int i = 0; i < 4; i++)
        #pragma unroll
        for (int j = 0; j < 4; j++)
            #pragma unroll
            for (int q = 0; q < 4; q++) acc[i][j][q] = 0.f;

    const int nkc = 72;           // 2304/32
    const int nit = 216;
    uint4 ra0, ra1, rb0, rb1;

    auto fetch = [&](int it) {
        int prod = (it < nkc) ? 0 : ((it < 2*nkc) ? 1 : 2);
        int kc   = it - prod * nkc;
        int kpos = kc << 5;
        int tap  = kc >> 3;              // 8 chunks of 32 per 256-wide tap
        int ci   = (kpos & 255) + colh;
        int dy = tap / 3 - 1;
        int dx = tap % 3 - 1;
        const __nv_bfloat16* As = (prod < 2) ? g_fb_h : g_fb_l;
        const __nv_bfloat16* Bs = (prod == 1) ? g_bd_l : g_bd_h;
        int yy = ay + dy, xx = ax + dx;
        ra0 = make_uint4(0, 0, 0, 0);
        ra1 = make_uint4(0, 0, 0, 0);
        if (yy >= 0 && yy < 32 && xx >= 0 && xx < 32) {
            const __nv_bfloat16* p = As + (size_t)((an << 10) + (yy << 5) + xx) * 256 + ci;
            ra0 = *(const uint4*)(p);
            ra1 = *(const uint4*)(p + 8);
        }
        const __nv_bfloat16* bp = Bs + (size_t)(bn + r0) * 2304 + kpos + colh;
        rb0 = *(const uint4*)(bp);
        rb1 = *(const uint4*)(bp + 8);
    };
    auto put = [&](int buf) {
        *(uint4*)&sA[buf][r0][colh]     = ra0;
        *(uint4*)&sA[buf][r0][colh + 8] = ra1;
        *(uint4*)&sB[buf][r0][colh]     = rb0;
        *(uint4*)&sB[buf][r0][colh + 8] = rb1;
    };

    fetch(0); put(0); __syncthreads();
    for (int it = 0; it < nit; it++) {
        int cur = it & 1;
        if (it + 1 < nit) fetch(it + 1);
        compute_tile(sA[cur], sB[cur], acc, wm, wn, lane);
        if (it + 1 < nit) put(cur ^ 1);
        __syncthreads();
    }

    const int group = lane >> 2, tig = lane & 3;
    #pragma unroll
    for (int mf = 0; mf < 4; mf++)
        #pragma unroll
        for (int nf = 0; nf < 4; nf++) {
            int col = bn + wn + nf*8 + tig*2;
            #pragma unroll
            for (int h2 = 0; h2 < 2; h2++) {
                int row = bm + wm + mf*16 + group + h2*8;
                int n2 = row >> 10, p2 = row & 1023;
                int y2 = p2 >> 5, x2 = p2 & 31;
                int ty = (y2 == 0) ? 0 : ((y2 == 31) ? 2 : 1);
                int tx = (x2 == 0) ? 0 : ((x2 == 31) ? 2 : 1);
                const float* Hrow = g_Hb + (n2 * 9 + ty * 3 + tx) * 256;
                const float* Srow = g_Sb + p2 * 256;
                float v0 = fmaxf(acc[mf][nf][h2*2+0] + Srow[col]   + Hrow[col],   0.f);
                float v1 = fmaxf(acc[mf][nf][h2*2+1] + Srow[col+1] + Hrow[col+1], 0.f);
                *(float2*)(g_t + (size_t)row * 256 + col) = make_float2(v0, v1);
            }
        }
}

// ---------------- layernorm (warp per row); writes fp32 + bf16 hi/lo ---------
__global__ void ln_split(const float* __restrict__ X, const float* __restrict__ g,
                         const float* __restrict__ b, float* __restrict__ Y,
                         __nv_bfloat16* __restrict__ Yh, __nv_bfloat16* __restrict__ Yl) {
    int warp = (blockIdx.x * blockDim.x + threadIdx.x) >> 5;
    int lane = threadIdx.x & 31;
    if (warp >= 16384) return;
    const float* xr = X + (size_t)warp * 256;
    float v[8], s = 0.f, s2 = 0.f;
    #pragma unroll
    for (int j = 0; j < 8; j++) {
        v[j] = xr[j * 32 + lane];
        s += v[j]; s2 += v[j] * v[j];
    }
    #pragma unroll
    for (int o = 16; o > 0; o >>= 1) {
        s  += __shfl_xor_sync(0xffffffffu, s, o);
        s2 += __shfl_xor_sync(0xffffffffu, s2, o);
    }
    float mean = s * (1.f / 256.f);
    float var  = s2 * (1.f / 256.f) - mean * mean;
    float inv  = rsqrtf(var + 1e-5f);
    #pragma unroll
    for (int j = 0; j < 8; j++) {
        int c = j * 32 + lane;
        float y = (v[j] - mean) * inv * g[c] + b[c];
        size_t o = (size_t)warp * 256 + c;
        Y[o] = y;
        __nv_bfloat16 h, l; split_bf16(y, h, l);
        Yh[o] = h; Yl[o] = l;
    }
}

// final LN + gated commit: updates feat bf16 hi/lo ONLY (dout written once at end)
__global__ void ln_gate(const float* __restrict__ X, const float* __restrict__ g,
                        const float* __restrict__ b, const int* __restrict__ words,
                        int s) {
    if (words[s] == 0) return;
    int warp = (blockIdx.x * blockDim.x + threadIdx.x) >> 5;
    int lane = threadIdx.x & 31;
    if (warp >= 16384) return;
    const float* xr = X + (size_t)warp * 256;
    float v[8], sm = 0.f, s2 = 0.f;
    #pragma unroll
    for (int j = 0; j < 8; j++) {
        v[j] = xr[j * 32 + lane];
        sm += v[j]; s2 += v[j] * v[j];
    }
    #pragma unroll
    for (int o = 16; o > 0; o >>= 1) {
        sm += __shfl_xor_sync(0xffffffffu, sm, o);
        s2 += __shfl_xor_sync(0xffffffffu, s2, o);
    }
    float mean = sm * (1.f / 256.f);
    float var  = s2 * (1.f / 256.f) - mean * mean;
    float inv  = rsqrtf(var + 1e-5f);
    #pragma unroll
    for (int j = 0; j < 8; j++) {
        int c = j * 32 + lane;
        float y = (v[j] - mean) * inv * g[c] + b[c];
        size_t o = (size_t)warp * 256 + c;
        __nv_bfloat16 h, l; split_bf16(y, h, l);
        g_fb_h[o] = h; g_fb_l[o] = l;
    }
}

// ---------------- final output: (n,p,c) bf16 hi/lo -> dout NCHW, coalesced ----
// grid: (16 p-tiles, 8 c-tiles, 16 n), 256 threads. smem 32x64 transpose tile.
__global__ void k_final_out(float* __restrict__ dout) {
    __shared__ float tile[32][65];
    const int pt = blockIdx.x;   // p0 = pt*64
    const int ct = blockIdx.y;   // c0 = ct*32
    const int n  = blockIdx.z;
    const int t  = threadIdx.x;
    #pragma unroll
    for (int i = 0; i < 8; i++) {
        int idx = t + i * 256;
        int c = idx & 31, p = idx >> 5;          // p in [0,64)
        size_t o = (size_t)((n << 10) + pt * 64 + p) * 256 + ct * 32 + c;
        tile[c][p] = __bfloat162float(g_fb_h[o]) + __bfloat162float(g_fb_l[o]);
    }
    __syncthreads();
    #pragma unroll
    for (int i = 0; i < 8; i++) {
        int idx = t + i * 256;
        int p = idx & 63, c = idx >> 6;          // c in [0,32)
        dout[(size_t)n * 262144 + (size_t)(ct * 32 + c) * 1024 + pt * 64 + p] = tile[c][p];
    }
}

// ---------------- cross-batch attention per (position, head) -----------------
__global__ void attn_kernel(int s) {
    const int p = blockIdx.x;
    const int h = blockIdx.y;
    __shared__ float qs[16][128];
    __shared__ float ks[16][129];
    __shared__ float vs[16][129];
    __shared__ float sc[16][16];
    const int tid = threadIdx.x;

    for (int i = tid; i < 16 * 128; i += 256) {
        int m = i >> 7, d = i & 127;
        qs[m][d] = g_qh[(size_t)(m * 20 + s) * 256 + h * 128 + d];
        const float* kvp = g_kv + (size_t)((m << 10) + p) * 512 + h * 128 + d;
        ks[m][d] = kvp[0];
        vs[m][d] = kvp[256];
    }
    __syncthreads();
    {
        int l = tid >> 4, m = tid & 15;
        float dot = 0.f;
        #pragma unroll
        for (int d = 0; d < 128; d++) dot += qs[l][d] * ks[m][d];
        sc[l][m] = dot * 0.08838834764831845f;
    }
    __syncthreads();
    if (tid < 16) {
        float mx = -1e30f;
        #pragma unroll
        for (int m = 0; m < 16; m++) mx = fmaxf(mx, sc[tid][m]);
        float sum = 0.f;
        #pragma unroll
        for (int m = 0; m < 16; m++) { float e = expf(sc[tid][m] - mx); sc[tid][m] = e; sum += e; }
        float inv = 1.f / sum;
        #pragma unroll
        for (int m = 0; m < 16; m++) sc[tid][m] *= inv;
    }
    __syncthreads();
    for (int i = tid; i < 16 * 128; i += 256) {
        int l = i >> 7, d = i & 127;
        float o = 0.f;
        #pragma unroll
        for (int m = 0; m < 16; m++) o += sc[l][m] * vs[m][d];
        size_t oidx = (size_t)((l << 10) + p) * 256 + h * 128 + d;
        __nv_bfloat16 hh, ll; split_bf16(o, hh, ll);
        g_ob_h[oidx] = hh; g_ob_l[oidx] = ll;
    }
}

// ============================================================================
// launch
// ============================================================================
extern "C" void kernel_launch(void* const* d_in, const int* in_sizes, int n_in,
                              void* d_out, int out_size) {
    (void)in_sizes; (void)n_in; (void)out_size;
    const float* hn        = (const float*)d_in[1];
    const float* feature   = (const float*)d_in[2];
    const float* embedding = (const float*)d_in[3];
    const int*   words     = (const int*)  d_in[4];
    const float* qconv_w   = (const float*)d_in[5];
    const float* qconv_b   = (const float*)d_in[6];
    const float* mconv_w   = (const float*)d_in[7];
    const float* mnorm_g   = (const float*)d_in[8];
    const float* mnorm_b   = (const float*)d_in[9];
    const float* in_proj_w = (const float*)d_in[10];
    const float* in_proj_b = (const float*)d_in[11];
    const float* out_proj_w= (const float*)d_in[12];
    const float* out_proj_b= (const float*)d_in[13];
    const float* norm_g    = (const float*)d_in[14];
    const float* norm_b    = (const float*)d_in[15];
    const float* lin1_w    = (const float*)d_in[16];
    const float* lin1_b    = (const float*)d_in[17];
    const float* lin2_w    = (const float*)d_in[18];
    const float* lin2_b    = (const float*)d_in[19];
    const float* normf_g   = (const float*)d_in[20];
    const float* normf_b   = (const float*)d_in[21];
    float* dout = (float*)d_out;

    float *p_t, *p_tln, *p_kv, *p_x1, *p_fea, *p_x2, *p_qt, *p_qh;
    __nv_bfloat16 *p_tlnh, *p_tlnl, *p_obh, *p_obl, *p_feah, *p_feal, *p_h1h, *p_h1l;
    __nv_bfloat16 *p_wih, *p_wil, *p_woh, *p_wol, *p_w1h, *p_w1l, *p_w2h, *p_w2l;
    cudaGetSymbolAddress((void**)&p_t,    g_t);
    cudaGetSymbolAddress((void**)&p_tln,  g_tln);
    cudaGetSymbolAddress((void**)&p_kv,   g_kv);
    cudaGetSymbolAddress((void**)&p_x1,   g_x1);
    cudaGetSymbolAddress((void**)&p_fea,  g_fea);
    cudaGetSymbolAddress((void**)&p_x2,   g_x2);
    cudaGetSymbolAddress((void**)&p_qt,   g_qt);
    cudaGetSymbolAddress((void**)&p_qh,   g_qh);
    cudaGetSymbolAddress((void**)&p_tlnh, g_tln_h);
    cudaGetSymbolAddress((void**)&p_tlnl, g_tln_l);
    cudaGetSymbolAddress((void**)&p_obh,  g_ob_h);
    cudaGetSymbolAddress((void**)&p_obl,  g_ob_l);
    cudaGetSymbolAddress((void**)&p_feah, g_fea_h);
    cudaGetSymbolAddress((void**)&p_feal, g_fea_l);
    cudaGetSymbolAddress((void**)&p_h1h,  g_h1_h);
    cudaGetSymbolAddress((void**)&p_h1l,  g_h1_l);
    cudaGetSymbolAddress((void**)&p_wih,  g_wi_h);
    cudaGetSymbolAddress((void**)&p_wil,  g_wi_l);
    cudaGetSymbolAddress((void**)&p_woh,  g_wo_h);
    cudaGetSymbolAddress((void**)&p_wol,  g_wo_l);
    cudaGetSymbolAddress((void**)&p_w1h,  g_w1_h);
    cudaGetSymbolAddress((void**)&p_w1l,  g_w1_l);
    cudaGetSymbolAddress((void**)&p_w2h,  g_w2_h);
    cudaGetSymbolAddress((void**)&p_w2l,  g_w2_l);

    const int T = 256;

    // ---- step-invariant precompute ----
    k_init_feat<<<DIV_UP(16*256*1024, T), T>>>(feature, dout);
    k_repack   <<<DIV_UP(256*2304,   T), T>>>(mconv_w);
    k_wsum     <<<DIV_UP(9*512*256,  T), T>>>(mconv_w);
    k_hb       <<<DIV_UP(16*9*256,   T), T>>>(hn);
    k_sb       <<<DIV_UP(1024*256,   T), T>>>(mconv_w);
    k_split<<<DIV_UP(768*256, T), T>>>(in_proj_w,  p_wih, p_wil, 768*256);
    k_split<<<DIV_UP(256*256, T), T>>>(out_proj_w, p_woh, p_wol, 256*256);
    k_split<<<DIV_UP(256*256, T), T>>>(lin1_w,     p_w1h, p_w1l, 256*256);
    k_split<<<DIV_UP(256*256, T), T>>>(lin2_w,     p_w2h, p_w2l, 256*256);
    gemm_nt<1,1><<<dim3(4,5), T>>>(embedding, qconv_w, qconv_b, p_qt, 320, 256, 300);
    gemm_nt<1,0><<<dim3(4,5), T>>>(p_qt, in_proj_w, in_proj_b, p_qh, 320, 256, 256);

    // ---- sequence loop ----
    for (int s = 0; s < 20; s++) {
        mma_conv<<<dim3(2, 128), T>>>();
        ln_split<<<2048, T>>>(p_t, mnorm_g, mnorm_b, p_tln, p_tlnh, p_tlnl);
        // fused K|V projection: rows 256..767 of in_proj, Nn=512
        mma_dense<0,0,0><<<dim3(4, 128), T>>>(p_tlnh, p_tlnl, p_wih + 256*256, p_wil + 256*256,
                                              256, 512, in_proj_b + 256, nullptr,
                                              p_kv, nullptr, nullptr);
        attn_kernel<<<dim3(1024, 2), T>>>(s);
        mma_dense<0,1,0><<<dim3(2, 128), T>>>(p_obh, p_obl, p_woh, p_wol,
                                              256, 256, out_proj_b, p_tln,
                                              p_x1, nullptr, nullptr);
        ln_split<<<2048, T>>>(p_x1, norm_g, norm_b, p_fea, p_feah, p_feal);
        mma_dense<1,0,1><<<dim3(2, 128), T>>>(p_feah, p_feal, p_w1h, p_w1l,
                                              256, 256, lin1_b, nullptr,
                                              nullptr, p_h1h, p_h1l);
        mma_dense<0,1,0><<<dim3(2, 128), T>>>(p_h1h, p_h1l, p_w2h, p_w2l,
                                              256, 256, lin2_b, p_fea,
                                              p_x2, nullptr, nullptr);
        ln_gate<<<2048, T>>>(p_x2, normf_g, normf_b, words, s);
    }

    // ---- single coalesced output write ----
    k_final_out<<<dim3(16, 8, 16), T>>>(dout);
}

// round 13
// speedup vs baseline: 1.2947x; 1.0020x over previous
#include <cuda_runtime.h>
#include <cuda_bf16.h>
#include <math.h>
#include <stdint.h>

// ============================================================================
// N=16, SEQ=20, P=32*32=1024, VD=256, HN=512, EMB=300, NHEAD=2, DH=128
// conv input channels: feat 0..255, spatial 256..263, hn 264..775
// Split-bf16 GEMM on mma.sync (HMMA): C = Ah*Bh + Ah*Bl + Al*Bh  (~1e-5 err)
// R12 (on R11 base, 10354us): (a) LN writes bf16 hi/lo only; GEMM residual
// reads hi/lo pair; (b) B-operand fragments via paired ldsm4 (8->6 LDSM/ks).
// ============================================================================

#define DIV_UP(a,b) (((a)+(b)-1)/(b))

__device__ __forceinline__ void split_bf16(float v, __nv_bfloat16& h, __nv_bfloat16& l) {
    h = __float2bfloat16(v);
    l = __float2bfloat16(v - __bfloat162float(h));
}

__device__ __forceinline__ void ldsm4(uint32_t* d, const void* p) {
    uint32_t addr = (uint32_t)__cvta_generic_to_shared(p);
    asm volatile("ldmatrix.sync.aligned.m8n8.x4.shared.b16 {%0,%1,%2,%3}, [%4];"
        : "=r"(d[0]), "=r"(d[1]), "=r"(d[2]), "=r"(d[3]) : "r"(addr));
}
__device__ __forceinline__ void mma16816(float* c, const uint32_t* a, const uint32_t* b) {
    asm volatile("mma.sync.aligned.m16n8k16.row.col.f32.bf16.bf16.f32 "
        "{%0,%1,%2,%3}, {%4,%5,%6,%7}, {%8,%9}, {%0,%1,%2,%3};"
        : "+f"(c[0]), "+f"(c[1]), "+f"(c[2]), "+f"(c[3])
        : "r"(a[0]), "r"(a[1]), "r"(a[2]), "r"(a[3]), "r"(b[0]), "r"(b[1]));
}

// ---------------- scratch (device globals) -----------------------------------
__device__ __nv_bfloat16 g_fb_h [16*1024*256], g_fb_l [16*1024*256];  // feat (n,p,c)
__device__ __nv_bfloat16 g_tln_h[16384*256],   g_tln_l[16384*256];
__device__ __nv_bfloat16 g_ob_h [16384*256],   g_ob_l [16384*256];
__device__ __nv_bfloat16 g_fea_h[16384*256],   g_fea_l[16384*256];
__device__ __nv_bfloat16 g_h1_h [16384*256],   g_h1_l [16384*256];
__device__ __nv_bfloat16 g_wi_h [768*256],     g_wi_l [768*256];      // in_proj
__device__ __nv_bfloat16 g_wo_h [256*256],     g_wo_l [256*256];
__device__ __nv_bfloat16 g_w1_h [256*256],     g_w1_l [256*256];
__device__ __nv_bfloat16 g_w2_h [256*256],     g_w2_l [256*256];
__device__ __nv_bfloat16 g_bd_h [256*2304],    g_bd_l [256*2304];     // conv weights
__device__ float g_t   [16384*256];
__device__ float g_kv  [16384*512];
__device__ float g_x1  [16384*256];
__device__ float g_x2  [16384*256];
__device__ float g_Wsum[9*512*256];
__device__ float g_Hb  [16*9*256];
__device__ float g_Sb  [1024*256];
__device__ float g_qt  [320*256];
__device__ float g_qh  [320*256];

// ---------------- init / precompute ------------------------------------------
__global__ void k_init_feat(const float* __restrict__ feature, float* __restrict__ dout) {
    int idx = blockIdx.x * blockDim.x + threadIdx.x;   // NCHW linear
    if (idx >= 16*256*1024) return;
    int n = idx >> 18;
    int r = idx & 262143;
    int c = r >> 10;
    int p = r & 1023;
    float v = feature[idx];
    dout[idx] = v;
    __nv_bfloat16 h, l; split_bf16(v, h, l);
    size_t o = (size_t)((n << 10) + p) * 256 + c;
    g_fb_h[o] = h; g_fb_l[o] = l;
}

__global__ void k_repack(const float* __restrict__ w) {
    int idx = blockIdx.x * blockDim.x + threadIdx.x;
    if (idx >= 256*2304) return;
    int co  = idx / 2304;
    int k   = idx % 2304;
    int tap = k >> 8;
    int ci  = k & 255;
    int kh = tap / 3, kw = tap % 3;
    float v = w[((co*776 + ci)*3 + kh)*3 + kw];
    __nv_bfloat16 h, l; split_bf16(v, h, l);
    g_bd_h[idx] = h; g_bd_l[idx] = l;
}

__global__ void k_split(const float* __restrict__ src, __nv_bfloat16* __restrict__ h,
                        __nv_bfloat16* __restrict__ l, int n) {
    int i = blockIdx.x * blockDim.x + threadIdx.x;
    if (i >= n) return;
    __nv_bfloat16 hh, ll; split_bf16(src[i], hh, ll);
    h[i] = hh; l[i] = ll;
}

__global__ void k_wsum(const float* __restrict__ w) {
    int idx = blockIdx.x * blockDim.x + threadIdx.x;
    if (idx >= 9*512*256) return;
    int co   = idx & 255;
    int tmp  = idx >> 8;
    int ci   = tmp & 511;
    int type = tmp >> 9;
    int ty = type / 3, tx = type % 3;
    int kh0 = (ty == 0) ? 1 : 0, kh1 = (ty == 2) ? 1 : 2;
    int kw0 = (tx == 0) ? 1 : 0, kw1 = (tx == 2) ? 1 : 2;
    float s = 0.f;
    for (int kh = kh0; kh <= kh1; kh++)
        for (int kw = kw0; kw <= kw1; kw++)
            s += w[((co*776 + 264 + ci)*3 + kh)*3 + kw];
    g_Wsum[idx] = s;
}

__global__ void k_hb(const float* __restrict__ hn) {
    int idx = blockIdx.x * blockDim.x + threadIdx.x;
    if (idx >= 16*9*256) return;
    int co   = idx & 255;
    int type = (idx >> 8) % 9;
    int n    = idx / 2304;
    const float* hr = hn + n * 512;
    const float* wr = g_Wsum + type * 512 * 256 + co;
    float s = 0.f;
    for (int ci = 0; ci < 512; ci++) s += hr[ci] * wr[ci * 256];
    g_Hb[idx] = s;
}

__device__ __forceinline__ float spatial_val(int ci, int yy, int xx) {
    const float inv = 1.f / 32.f;
    switch (ci) {
        case 0: return xx * (2.f*inv) - 1.f;
        case 1: return yy * (2.f*inv) - 1.f;
        case 2: return (xx + 1) * (2.f*inv) - 1.f;
        case 3: return (yy + 1) * (2.f*inv) - 1.f;
        case 4: return (xx + 0.5f) * (2.f*inv) - 1.f;
        case 5: return (yy + 0.5f) * (2.f*inv) - 1.f;
        default: return inv;
    }
}

__global__ void k_sb(const float* __restrict__ w) {
    int idx = blockIdx.x * blockDim.x + threadIdx.x;
    if (idx >= 1024*256) return;
    int co = idx & 255;
    int p  = idx >> 8;
    int y = p >> 5, x = p & 31;
    float s = 0.f;
    for (int kh = 0; kh < 3; kh++) {
        int yy = y + kh - 1;
        if (yy < 0 || yy > 31) continue;
        for (int kw = 0; kw < 3; kw++) {
            int xx = x + kw - 1;
            if (xx < 0 || xx > 31) continue;
            #pragma unroll
            for (int ci = 0; ci < 8; ci++)
                s += w[((co*776 + 256 + ci)*3 + kh)*3 + kw] * spatial_val(ci, yy, xx);
        }
    }
    g_Sb[p * 256 + co] = s;
}

// ---------------- small fp32 NT GEMM (precompute only) ------------------------
template<int DO_BIAS, int DO_RELU>
__global__ void gemm_nt(const float* __restrict__ A, const float* __restrict__ B,
                        const float* __restrict__ bias,
                        float* __restrict__ C, int M, int Nn, int K) {
    __shared__ float As[16][64];
    __shared__ float Bs[16][64];
    const int bm = blockIdx.y * 64;
    const int bn = blockIdx.x * 64;
    const int tid = threadIdx.x;
    const int lr = tid >> 2;
    const int lc = (tid & 3) * 4;
    const int tm = (tid >> 4) * 4;
    const int tn = (tid & 15) * 4;

    float acc[4][4];
    #pragma unroll
    for (int i = 0; i < 4; i++)
        #pragma unroll
        for (int j = 0; j < 4; j++) acc[i][j] = 0.f;

    for (int k0 = 0; k0 < K; k0 += 16) {
        float4 av = make_float4(0,0,0,0), bv = make_float4(0,0,0,0);
        int kk = k0 + lc;
        int ar = bm + lr;
        if (ar < M) {
            if (kk + 4 <= K) av = *(const float4*)(A + (size_t)ar * K + kk);
            else { float* q = (float*)&av;
                   for (int j = 0; j < 4; j++) if (kk + j < K) q[j] = A[(size_t)ar * K + kk + j]; }
        }
        int br = bn + lr;
        if (br < Nn) {
            if (kk + 4 <= K) bv = *(const float4*)(B + (size_t)br * K + kk);
            else { float* q = (float*)&bv;
                   for (int j = 0; j < 4; j++) if (kk + j < K) q[j] = B[(size_t)br * K + kk + j]; }
        }
        As[lc+0][lr] = av.x; As[lc+1][lr] = av.y; As[lc+2][lr] = av.z; As[lc+3][lr] = av.w;
        Bs[lc+0][lr] = bv.x; Bs[lc+1][lr] = bv.y; Bs[lc+2][lr] = bv.z; Bs[lc+3][lr] = bv.w;
        __syncthreads();
        #pragma unroll
        for (int k = 0; k < 16; k++) {
            float a[4], b[4];
            #pragma unroll
            for (int i = 0; i < 4; i++) a[i] = As[k][tm + i];
            #pragma unroll
            for (int j = 0; j < 4; j++) b[j] = Bs[k][tn + j];
            #pragma unroll
            for (int i = 0; i < 4; i++)
                #pragma unroll
                for (int j = 0; j < 4; j++) acc[i][j] += a[i] * b[j];
        }
        __syncthreads();
    }

    #pragma unroll
    for (int i = 0; i < 4; i++) {
        int row = bm + tm + i;
        if (row >= M) continue;
        #pragma unroll
        for (int j = 0; j < 4; j++) {
            int col = bn + tn + j;
            float v = acc[i][j];
            if (DO_BIAS) v += bias[col];
            if (DO_RELU) v = fmaxf(v, 0.f);
            C[(size_t)row * Nn + col] = v;
        }
    }
}

// ============================================================================
// mma.sync split-bf16 GEMM core (R8/R11 structure). CTA tile 128x128x32,
// 8 warps, warp tile 64x32. smem [128][40]; 3 sequential product passes over
// K; register-prefetch double buffering; __launch_bounds__(256,2).
// B fragments loaded as nf-pairs via ldsm4 (R12 change).
// ============================================================================

__device__ __forceinline__ void compute_tile(const __nv_bfloat16 (*sA)[40],
                                             const __nv_bfloat16 (*sB)[40],
                                             float acc[4][4][4], int wm, int wn, int lane) {
    const int r = lane & 7;
    const int t = lane >> 3;        // 0..3
    #pragma unroll
    for (int ks = 0; ks < 32; ks += 16) {
        uint32_t afr[4][4], bfr[4][2];
        #pragma unroll
        for (int mf = 0; mf < 4; mf++)
            ldsm4(afr[mf], &sA[wm + mf*16 + (t & 1)*8 + r][ks + (t >> 1)*8]);
        // B: nf-pair per ldsm4. Lane group m = t selects (nf offset, k half):
        //   m0 -> (nfp+0, k0), m1 -> (nfp+0, k8), m2 -> (nfp+1, k0), m3 -> (nfp+1, k8)
        #pragma unroll
        for (int nfp = 0; nfp < 4; nfp += 2) {
            uint32_t d[4];
            ldsm4(d, &sB[wn + (nfp + (t >> 1))*8 + r][ks + (t & 1)*8]);
            bfr[nfp  ][0] = d[0]; bfr[nfp  ][1] = d[1];
            bfr[nfp+1][0] = d[2]; bfr[nfp+1][1] = d[3];
        }
        #pragma unroll
        for (int mf = 0; mf < 4; mf++)
            #pragma unroll
            for (int nf = 0; nf < 4; nf++)
                mma16816(acc[mf][nf], afr[mf], bfr[nf]);
    }
}

// dense: A [M][K] bf16 hi/lo, B [Nn][K] bf16 hi/lo. grid = (Nn/128, M/128).
// RES: residual read from bf16 hi/lo pair (resh + resl).
template<int RELU, int RES, int BF16OUT>
__global__ void __launch_bounds__(256, 2)
mma_dense(const __nv_bfloat16* __restrict__ Ah, const __nv_bfloat16* __restrict__ Al,
          const __nv_bfloat16* __restrict__ Bh, const __nv_bfloat16* __restrict__ Bl,
          int K, int ostride,
          const float* __restrict__ bias,
          const __nv_bfloat16* __restrict__ resh, const __nv_bfloat16* __restrict__ resl,
          float* __restrict__ C, __nv_bfloat16* __restrict__ Ch, __nv_bfloat16* __restrict__ Cl) {
    __shared__ __align__(16) __nv_bfloat16 sA[2][128][40];
    __shared__ __align__(16) __nv_bfloat16 sB[2][128][40];
    const int tid = threadIdx.x;
    const int lane = tid & 31, warp = tid >> 5;
    const int wm = (warp >> 2) * 64, wn = (warp & 3) * 32;
    const int bm = blockIdx.y * 128, bn = blockIdx.x * 128;
    const int r0 = tid >> 1, colh = (tid & 1) * 16;

    float acc[4][4][4];
    #pragma unroll
    for (int i = 0; i < 4; i++)
        #pragma unroll
        for (int j = 0; j < 4; j++)
            #pragma unroll
            for (int q = 0; q < 4; q++) acc[i][j][q] = 0.f;

    const int nkc = K >> 5;
    const int nit = 3 * nkc;
    uint4 ra0, ra1, rb0, rb1;

    auto fetch = [&](int it) {
        int prod = (it < nkc) ? 0 : ((it < 2*nkc) ? 1 : 2);
        int kpos = (it - prod * nkc) << 5;
        const __nv_bfloat16* As = (prod < 2) ? Ah : Al;
        const __nv_bfloat16* Bs = (prod == 1) ? Bl : Bh;
        const __nv_bfloat16* ap = As + (size_t)(bm + r0) * K + kpos + colh;
        const __nv_bfloat16* bp = Bs + (size_t)(bn + r0) * K + kpos + colh;
        ra0 = *(const uint4*)(ap);
        ra1 = *(const uint4*)(ap + 8);
        rb0 = *(const uint4*)(bp);
        rb1 = *(const uint4*)(bp + 8);
    };
    auto put = [&](int buf) {
        *(uint4*)&sA[buf][r0][colh]     = ra0;
        *(uint4*)&sA[buf][r0][colh + 8] = ra1;
        *(uint4*)&sB[buf][r0][colh]     = rb0;
        *(uint4*)&sB[buf][r0][colh + 8] = rb1;
    };

    fetch(0); put(0); __syncthreads();
    for (int it = 0; it < nit; it++) {
        int cur = it & 1;
        if (it + 1 < nit) fetch(it + 1);
        compute_tile(sA[cur], sB[cur], acc, wm, wn, lane);
        if (it + 1 < nit) put(cur ^ 1);
        __syncthreads();
    }

    const int group = lane >> 2, tig = lane & 3;
    #pragma unroll
    for (int mf = 0; mf < 4; mf++)
        #pragma unroll
        for (int nf = 0; nf < 4; nf++) {
            int col = bn + wn + nf*8 + tig*2;
            #pragma unroll
            for (int h2 = 0; h2 < 2; h2++) {
                int row = bm + wm + mf*16 + group + h2*8;
                float v0 = acc[mf][nf][h2*2+0] + bias[col];
                float v1 = acc[mf][nf][h2*2+1] + bias[col+1];
                if (RES) {
                    size_t ro = (size_t)row * 256 + col;
                    v0 += __bfloat162float(resh[ro])   + __bfloat162float(resl[ro]);
                    v1 += __bfloat162float(resh[ro+1]) + __bfloat162float(resl[ro+1]);
                }
                if (RELU) { v0 = fmaxf(v0, 0.f); v1 = fmaxf(v1, 0.f); }
                if (BF16OUT) {
                    __nv_bfloat16 h, l;
                    split_bf16(v0, h, l);
                    Ch[(size_t)row * 256 + col] = h; Cl[(size_t)row * 256 + col] = l;
                    split_bf16(v1, h, l);
                    Ch[(size_t)row * 256 + col + 1] = h; Cl[(size_t)row * 256 + col + 1] = l;
                } else {
                    *(float2*)(C + (size_t)row * ostride + col) = make_float2(v0, v1);
                }
            }
        }
}

// conv: implicit GEMM, A gathered from g_fb_{h,l} (K=2304, tap-major),
// B = g_bd_{h,l}. Epilogue +Sb +Hb, relu -> g_t. grid = (2, 128).
__global__ void __launch_bounds__(256, 2)
mma_conv() {
    __shared__ __align__(16) __nv_bfloat16 sA[2][128][40];
    __shared__ __align__(16) __nv_bfloat16 sB[2][128][40];
    const int tid = threadIdx.x;
    const int lane = tid & 31, warp = tid >> 5;
    const int wm = (warp >> 2) * 64, wn = (warp & 3) * 32;
    const int bm = blockIdx.y * 128, bn = blockIdx.x * 128;
    const int r0 = tid >> 1, colh = (tid & 1) * 16;

    const int arow = bm + r0;
    const int an = arow >> 10, ap_ = arow & 1023;
    const int ay = ap_ >> 5, ax = ap_ & 31;

    float acc[4][4][4];
    #pragma unroll
    for (int i = 0; i < 4; i++)
        #pragma unroll
        for (int j = 0; j < 4; j++)
            #pragma unroll
            for (int q = 0; q < 4; q++) acc[i][j][q] = 0.f;

    const int nkc = 72;           // 2304/32
    const int nit = 216;
    uint4 ra0, ra1, rb0, rb1;

    auto fetch = [&](int it) {
        int prod = (it < nkc) ? 0 : ((it < 2*nkc) ? 1 : 2);
        int kc   = it - prod * nkc;
        int kpos = kc << 5;
        int tap  = kc >> 3;
        int ci   = (kpos & 255) + colh;
        int dy = tap / 3 - 1;
        int dx = tap % 3 - 1;
        const __nv_bfloat16* As = (prod < 2) ? g_fb_h : g_fb_l;
        const __nv_bfloat16* Bs = (prod == 1) ? g_bd_l : g_bd_h;
        int yy = ay + dy, xx = ax + dx;
        ra0 = make_uint4(0, 0, 0, 0);
        ra1 = make_uint4(0, 0, 0, 0);
        if (yy >= 0 && yy < 32 && xx >= 0 && xx < 32) {
            const __nv_bfloat16* p = As + (size_t)((an << 10) + (yy << 5) + xx) * 256 + ci;
            ra0 = *(const uint4*)(p);
            ra1 = *(const uint4*)(p + 8);
        }
        const __nv_bfloat16* bp = Bs + (size_t)(bn + r0) * 2304 + kpos + colh;
        rb0 = *(const uint4*)(bp);
        rb1 = *(const uint4*)(bp + 8);
    };
    auto put = [&](int buf) {
        *(uint4*)&sA[buf][r0][colh]     = ra0;
        *(uint4*)&sA[buf][r0][colh + 8] = ra1;
        *(uint4*)&sB[buf][r0][colh]     = rb0;
        *(uint4*)&sB[buf][r0][colh + 8] = rb1;
    };

    fetch(0); put(0); __syncthreads();
    for (int it = 0; it < nit; it++) {
        int cur = it & 1;
        if (it + 1 < nit) fetch(it + 1);
        compute_tile(sA[cur], sB[cur], acc, wm, wn, lane);
        if (it + 1 < nit) put(cur ^ 1);
        __syncthreads();
    }

    const int group = lane >> 2, tig = lane & 3;
    #pragma unroll
    for (int mf = 0; mf < 4; mf++)
        #pragma unroll
        for (int nf = 0; nf < 4; nf++) {
            int col = bn + wn + nf*8 + tig*2;
            #pragma unroll
            for (int h2 = 0; h2 < 2; h2++) {
                int row = bm + wm + mf*16 + group + h2*8;
                int n2 = row >> 10, p2 = row & 1023;
                int y2 = p2 >> 5, x2 = p2 & 31;
                int ty = (y2 == 0) ? 0 : ((y2 == 31) ? 2 : 1);
                int tx = (x2 == 0) ? 0 : ((x2 == 31) ? 2 : 1);
                const float* Hrow = g_Hb + (n2 * 9 + ty * 3 + tx) * 256;
                const float* Srow = g_Sb + p2 * 256;
                float v0 = fmaxf(acc[mf][nf][h2*2+0] + Srow[col]   + Hrow[col],   0.f);
                float v1 = fmaxf(acc[mf][nf][h2*2+1] + Srow[col+1] + Hrow[col+1], 0.f);
                *(float2*)(g_t + (size_t)row * 256 + col) = make_float2(v0, v1);
            }
        }
}

// ---------------- layernorm (warp per row); writes bf16 hi/lo only -----------
__global__ void ln_split(const float* __restrict__ X, const float* __restrict__ g,
                         const float* __restrict__ b,
                         __nv_bfloat16* __restrict__ Yh, __nv_bfloat16* __restrict__ Yl) {
    int warp = (blockIdx.x * blockDim.x + threadIdx.x) >> 5;
    int lane = threadIdx.x & 31;
    if (warp >= 16384) return;
    const float* xr = X + (size_t)warp * 256;
    float v[8], s = 0.f, s2 = 0.f;
    #pragma unroll
    for (int j = 0; j < 8; j++) {
        v[j] = xr[j * 32 + lane];
        s += v[j]; s2 += v[j] * v[j];
    }
    #pragma unroll
    for (int o = 16; o > 0; o >>= 1) {
        s  += __shfl_xor_sync(0xffffffffu, s, o);
        s2 += __shfl_xor_sync(0xffffffffu, s2, o);
    }
    float mean = s * (1.f / 256.f);
    float var  = s2 * (1.f / 256.f) - mean * mean;
    float inv  = rsqrtf(var + 1e-5f);
    #pragma unroll
    for (int j = 0; j < 8; j++) {
        int c = j * 32 + lane;
        float y = (v[j] - mean) * inv * g[c] + b[c];
        size_t o = (size_t)warp * 256 + c;
        __nv_bfloat16 h, l; split_bf16(y, h, l);
        Yh[o] = h; Yl[o] = l;
    }
}

// final LN + gated commit: updates feat bf16 hi/lo ONLY (dout written once at end)
__global__ void ln_gate(const float* __restrict__ X, const float* __restrict__ g,
                        const float* __restrict__ b, const int* __restrict__ words,
                        int s) {
    if (words[s] == 0) return;
    int warp = (blockIdx.x * blockDim.x + threadIdx.x) >> 5;
    int lane = threadIdx.x & 31;
    if (warp >= 16384) return;
    const float* xr = X + (size_t)warp * 256;
    float v[8], sm = 0.f, s2 = 0.f;
    #pragma unroll
    for (int j = 0; j < 8; j++) {
        v[j] = xr[j * 32 + lane];
        sm += v[j]; s2 += v[j] * v[j];
    }
    #pragma unroll
    for (int o = 16; o > 0; o >>= 1) {
        sm += __shfl_xor_sync(0xffffffffu, sm, o);
        s2 += __shfl_xor_sync(0xffffffffu, s2, o);
    }
    float mean = sm * (1.f / 256.f);
    float var  = s2 * (1.f / 256.f) - mean * mean;
    float inv  = rsqrtf(var + 1e-5f);
    #pragma unroll
    for (int j = 0; j < 8; j++) {
        int c = j * 32 + lane;
        float y = (v[j] - mean) * inv * g[c] + b[c];
        size_t o = (size_t)warp * 256 + c;
        __nv_bfloat16 h, l; split_bf16(y, h, l);
        g_fb_h[o] = h; g_fb_l[o] = l;
    }
}

// ---------------- final output: (n,p,c) bf16 hi/lo -> dout NCHW, coalesced ----
__global__ void k_final_out(float* __restrict__ dout) {
    __shared__ float tile[32][65];
    const int pt = blockIdx.x;
    const int ct = blockIdx.y;
    const int n  = blockIdx.z;
    const int t  = threadIdx.x;
    #pragma unroll
    for (int i = 0; i < 8; i++) {
        int idx = t + i * 256;
        int c = idx & 31, p = idx >> 5;
        size_t o = (size_t)((n << 10) + pt * 64 + p) * 256 + ct * 32 + c;
        tile[c][p] = __bfloat162float(g_fb_h[o]) + __bfloat162float(g_fb_l[o]);
    }
    __syncthreads();
    #pragma unroll
    for (int i = 0; i < 8; i++) {
        int idx = t + i * 256;
        int p = idx & 63, c = idx >> 6;
        dout[(size_t)n * 262144 + (size_t)(ct * 32 + c) * 1024 + pt * 64 + p] = tile[c][p];
    }
}

// ---------------- cross-batch attention per (position, head) -----------------
__global__ void attn_kernel(int s) {
    const int p = blockIdx.x;
    const int h = blockIdx.y;
    __shared__ float qs[16][128];
    __shared__ float ks[16][129];
    __shared__ float vs[16][129];
    __shared__ float sc[16][16];
    const int tid = threadIdx.x;

    for (int i = tid; i < 16 * 128; i += 256) {
        int m = i >> 7, d = i & 127;
        qs[m][d] = g_qh[(size_t)(m * 20 + s) * 256 + h * 128 + d];
        const float* kvp = g_kv + (size_t)((m << 10) + p) * 512 + h * 128 + d;
        ks[m][d] = kvp[0];
        vs[m][d] = kvp[256];
    }
    __syncthreads();
    {
        int l = tid >> 4, m = tid & 15;
        float dot = 0.f;
        #pragma unroll
        for (int d = 0; d < 128; d++) dot += qs[l][d] * ks[m][d];
        sc[l][m] = dot * 0.08838834764831845f;
    }
    __syncthreads();
    if (tid < 16) {
        float mx = -1e30f;
        #pragma unroll
        for (int m = 0; m < 16; m++) mx = fmaxf(mx, sc[tid][m]);
        float sum = 0.f;
        #pragma unroll
        for (int m = 0; m < 16; m++) { float e = expf(sc[tid][m] - mx); sc[tid][m] = e; sum += e; }
        float inv = 1.f / sum;
        #pragma unroll
        for (int m = 0; m < 16; m++) sc[tid][m] *= inv;
    }
    __syncthreads();
    for (int i = tid; i < 16 * 128; i += 256) {
        int l = i >> 7, d = i & 127;
        float o = 0.f;
        #pragma unroll
        for (int m = 0; m < 16; m++) o += sc[l][m] * vs[m][d];
        size_t oidx = (size_t)((l << 10) + p) * 256 + h * 128 + d;
        __nv_bfloat16 hh, ll; split_bf16(o, hh, ll);
        g_ob_h[oidx] = hh; g_ob_l[oidx] = ll;
    }
}

// ============================================================================
// launch
// ============================================================================
extern "C" void kernel_launch(void* const* d_in, const int* in_sizes, int n_in,
                              void* d_out, int out_size) {
    (void)in_sizes; (void)n_in; (void)out_size;
    const float* hn        = (const float*)d_in[1];
    const float* feature   = (const float*)d_in[2];
    const float* embedding = (const float*)d_in[3];
    const int*   words     = (const int*)  d_in[4];
    const float* qconv_w   = (const float*)d_in[5];
    const float* qconv_b   = (const float*)d_in[6];
    const float* mconv_w   = (const float*)d_in[7];
    const float* mnorm_g   = (const float*)d_in[8];
    const float* mnorm_b   = (const float*)d_in[9];
    const float* in_proj_w = (const float*)d_in[10];
    const float* in_proj_b = (const float*)d_in[11];
    const float* out_proj_w= (const float*)d_in[12];
    const float* out_proj_b= (const float*)d_in[13];
    const float* norm_g    = (const float*)d_in[14];
    const float* norm_b    = (const float*)d_in[15];
    const float* lin1_w    = (const float*)d_in[16];
    const float* lin1_b    = (const float*)d_in[17];
    const float* lin2_w    = (const float*)d_in[18];
    const float* lin2_b    = (const float*)d_in[19];
    const float* normf_g   = (const float*)d_in[20];
    const float* normf_b   = (const float*)d_in[21];
    float* dout = (float*)d_out;

    float *p_t, *p_kv, *p_x1, *p_x2, *p_qt, *p_qh;
    __nv_bfloat16 *p_tlnh, *p_tlnl, *p_obh, *p_obl, *p_feah, *p_feal, *p_h1h, *p_h1l;
    __nv_bfloat16 *p_wih, *p_wil, *p_woh, *p_wol, *p_w1h, *p_w1l, *p_w2h, *p_w2l;
    cudaGetSymbolAddress((void**)&p_t,    g_t);
    cudaGetSymbolAddress((void**)&p_kv,   g_kv);
    cudaGetSymbolAddress((void**)&p_x1,   g_x1);
    cudaGetSymbolAddress((void**)&p_x2,   g_x2);
    cudaGetSymbolAddress((void**)&p_qt,   g_qt);
    cudaGetSymbolAddress((void**)&p_qh,   g_qh);
    cudaGetSymbolAddress((void**)&p_tlnh, g_tln_h);
    cudaGetSymbolAddress((void**)&p_tlnl, g_tln_l);
    cudaGetSymbolAddress((void**)&p_obh,  g_ob_h);
    cudaGetSymbolAddress((void**)&p_obl,  g_ob_l);
    cudaGetSymbolAddress((void**)&p_feah, g_fea_h);
    cudaGetSymbolAddress((void**)&p_feal, g_fea_l);
    cudaGetSymbolAddress((void**)&p_h1h,  g_h1_h);
    cudaGetSymbolAddress((void**)&p_h1l,  g_h1_l);
    cudaGetSymbolAddress((void**)&p_wih,  g_wi_h);
    cudaGetSymbolAddress((void**)&p_wil,  g_wi_l);
    cudaGetSymbolAddress((void**)&p_woh,  g_wo_h);
    cudaGetSymbolAddress((void**)&p_wol,  g_wo_l);
    cudaGetSymbolAddress((void**)&p_w1h,  g_w1_h);
    cudaGetSymbolAddress((void**)&p_w1l,  g_w1_l);
    cudaGetSymbolAddress((void**)&p_w2h,  g_w2_h);
    cudaGetSymbolAddress((void**)&p_w2l,  g_w2_l);

    const int T = 256;

    // ---- step-invariant precompute ----
    k_init_feat<<<DIV_UP(16*256*1024, T), T>>>(feature, dout);
    k_repack   <<<DIV_UP(256*2304,   T), T>>>(mconv_w);
    k_wsum     <<<DIV_UP(9*512*256,  T), T>>>(mconv_w);
    k_hb       <<<DIV_UP(16*9*256,   T), T>>>(hn);
    k_sb       <<<DIV_UP(1024*256,   T), T>>>(mconv_w);
    k_split<<<DIV_UP(768*256, T), T>>>(in_proj_w,  p_wih, p_wil, 768*256);
    k_split<<<DIV_UP(256*256, T), T>>>(out_proj_w, p_woh, p_wol, 256*256);
    k_split<<<DIV_UP(256*256, T), T>>>(lin1_w,     p_w1h, p_w1l, 256*256);
    k_split<<<DIV_UP(256*256, T), T>>>(lin2_w,     p_w2h, p_w2l, 256*256);
    gemm_nt<1,1><<<dim3(4,5), T>>>(embedding, qconv_w, qconv_b, p_qt, 320, 256, 300);
    gemm_nt<1,0><<<dim3(4,5), T>>>(p_qt, in_proj_w, in_proj_b, p_qh, 320, 256, 256);

    // ---- sequence loop ----
    for (int s = 0; s < 20; s++) {
        mma_conv<<<dim3(2, 128), T>>>();
        ln_split<<<2048, T>>>(p_t, mnorm_g, mnorm_b, p_tlnh, p_tlnl);
        // fused K|V projection: rows 256..767 of in_proj, Nn=512
        mma_dense<0,0,0><<<dim3(4, 128), T>>>(p_tlnh, p_tlnl, p_wih + 256*256, p_wil + 256*256,
                                              256, 512, in_proj_b + 256, nullptr, nullptr,
                                              p_kv, nullptr, nullptr);
        attn_kernel<<<dim3(1024, 2), T>>>(s);
        mma_dense<0,1,0><<<dim3(2, 128), T>>>(p_obh, p_obl, p_woh, p_wol,
                                              256, 256, out_proj_b, p_tlnh, p_tlnl,
                                              p_x1, nullptr, nullptr);
        ln_split<<<2048, T>>>(p_x1, norm_g, norm_b, p_feah, p_feal);
        mma_dense<1,0,1><<<dim3(2, 128), T>>>(p_feah, p_feal, p_w1h, p_w1l,
                                              256, 256, lin1_b, nullptr, nullptr,
                                              nullptr, p_h1h, p_h1l);
        mma_dense<0,1,0><<<dim3(2, 128), T>>>(p_h1h, p_h1l, p_w2h, p_w2l,
                                              256, 256, lin2_b, p_feah, p_feal,
                                              p_x2, nullptr, nullptr);
        ln_gate<<<2048, T>>>(p_x2, normf_g, normf_b, words, s);
    }

    // ---- single coalesced output write ----
    k_final_out<<<dim3(16, 8, 16), T>>>(dout);
}